// round 5
// baseline (speedup 1.0000x reference)
#include <cuda_runtime.h>
#include <cuda_bf16.h>
#include <cstdint>

#define D256 256
#define NMAX 100000
#define EMAX 1600000
#define SCAN_BLK 1024

// ---------------- scratch (device globals) ----------------
__device__ float g_x[(size_t)NMAX * D256];      // fp32 x (for aggregation L1)
__device__ float g_h[(size_t)NMAX * D256];      // fp32 h (for aggregation L2)
__device__ float g_cr[(size_t)NMAX * D256];     // r-part partial (x@Wr)
__device__ __nv_bfloat16 g_xhi[(size_t)NMAX * D256];
__device__ __nv_bfloat16 g_xlo[(size_t)NMAX * D256];
__device__ __nv_bfloat16 g_hhi[(size_t)NMAX * D256];
__device__ __nv_bfloat16 g_hlo[(size_t)NMAX * D256];
__device__ __nv_bfloat16 g_mhi[(size_t)NMAX * D256];
__device__ __nv_bfloat16 g_mlo[(size_t)NMAX * D256];
__device__ int   g_cnt[NMAX + 1];
__device__ int   g_incl[NMAX + 1];
__device__ int   g_rowptr[NMAX + 2];
__device__ int   g_wptr[NMAX + 1];
__device__ int   g_col[EMAX];
__device__ int   g_part[256];
__device__ int   g_poff[256];
// pre-converted weights: [layer][n (256)][k (512)] bf16 hi/lo (k<256: Wl, k>=256: Wr)
__device__ __nv_bfloat16 g_Bhi[2 * 256 * 512];
__device__ __nv_bfloat16 g_Blo[2 * 256 * 512];

// ---------------- helpers ----------------
__device__ __forceinline__ float bf_hi(float v) {
    return __bfloat162float(__float2bfloat16_rn(v));
}
__device__ __forceinline__ uint32_t pk(float a, float b) {
    uint32_t lo = __bfloat16_as_ushort(__float2bfloat16_rn(a));
    uint32_t hi = __bfloat16_as_ushort(__float2bfloat16_rn(b));
    return lo | (hi << 16);
}
__device__ __forceinline__ uint32_t smem_u32(const void* p) {
    uint32_t a;
    asm("{ .reg .u64 t; cvta.to.shared.u64 t, %1; cvt.u32.u64 %0, t; }"
        : "=r"(a) : "l"(p));
    return a;
}
__device__ __forceinline__ void mma_bf16(float* c, const uint32_t* a, const uint32_t* b) {
    asm volatile(
        "mma.sync.aligned.m16n8k16.row.col.f32.bf16.bf16.f32 "
        "{%0,%1,%2,%3}, {%4,%5,%6,%7}, {%8,%9}, {%0,%1,%2,%3};"
        : "+f"(c[0]), "+f"(c[1]), "+f"(c[2]), "+f"(c[3])
        : "r"(a[0]), "r"(a[1]), "r"(a[2]), "r"(a[3]), "r"(b[0]), "r"(b[1]));
}
__device__ __forceinline__ void ldsm_x4(uint32_t* r, uint32_t addr) {
    asm volatile("ldmatrix.sync.aligned.m8n8.x4.shared.b16 {%0,%1,%2,%3}, [%4];"
                 : "=r"(r[0]), "=r"(r[1]), "=r"(r[2]), "=r"(r[3]) : "r"(addr));
}
#define CP_ASYNC16(dst, src) asm volatile( \
    "cp.async.cg.shared.global [%0], [%1], 16;" :: "r"(dst), "l"(src) : "memory")
#define CP_COMMIT() asm volatile("cp.async.commit_group;" ::: "memory")
#define CP_WAIT0() asm volatile("cp.async.wait_group 0;" ::: "memory")

// ---------------- small utility kernels ----------------
__global__ void zero_cnt_kernel(int n) {
    int i = blockIdx.x * blockDim.x + threadIdx.x;
    if (i < n) g_cnt[i] = 0;
}
__global__ void gather_x_kernel(const float* __restrict__ emb,
                                const int* __restrict__ idx, int N) {
    int t = blockIdx.x * blockDim.x + threadIdx.x;
    if (t >= N * 32) return;
    int r = t >> 5, c = t & 31;
    const float4* p = (const float4*)emb + (size_t)idx[r] * 64 + c * 2;
    float4 v0 = p[0], v1 = p[1];
    size_t eo = (size_t)r * 64 + c * 2;
    ((float4*)g_x)[eo] = v0;
    ((float4*)g_x)[eo + 1] = v1;
    float h0 = bf_hi(v0.x), h1 = bf_hi(v0.y), h2 = bf_hi(v0.z), h3 = bf_hi(v0.w);
    float h4 = bf_hi(v1.x), h5 = bf_hi(v1.y), h6 = bf_hi(v1.z), h7 = bf_hi(v1.w);
    ((uint4*)g_xhi)[(size_t)r * 32 + c] =
        make_uint4(pk(h0, h1), pk(h2, h3), pk(h4, h5), pk(h6, h7));
    ((uint4*)g_xlo)[(size_t)r * 32 + c] =
        make_uint4(pk(v0.x - h0, v0.y - h1), pk(v0.z - h2, v0.w - h3),
                   pk(v1.x - h4, v1.y - h5), pk(v1.z - h6, v1.w - h7));
}
__global__ void hist_kernel(const int* __restrict__ dst, int E) {
    int i = blockIdx.x * blockDim.x + threadIdx.x;
    if (i < E) atomicAdd(&g_cnt[dst[i]], 1);
}
__global__ void scan_local_kernel(int N) {
    __shared__ int s[SCAN_BLK];
    int i = blockIdx.x * SCAN_BLK + threadIdx.x;
    int v = (i < N) ? g_cnt[i] : 0;
    s[threadIdx.x] = v;
    __syncthreads();
    for (int off = 1; off < SCAN_BLK; off <<= 1) {
        int t = (threadIdx.x >= off) ? s[threadIdx.x - off] : 0;
        __syncthreads();
        s[threadIdx.x] += t;
        __syncthreads();
    }
    if (i < N) g_incl[i] = s[threadIdx.x];
    if (threadIdx.x == SCAN_BLK - 1) g_part[blockIdx.x] = s[SCAN_BLK - 1];
}
__global__ void scan_part_kernel(int nb) {
    int run = 0;
    for (int b = 0; b < nb; b++) { g_poff[b] = run; run += g_part[b]; }
}
__global__ void scan_final_kernel(int N) {
    int i = blockIdx.x * SCAN_BLK + threadIdx.x;
    if (i < N) {
        int v = g_incl[i] + g_poff[blockIdx.x];
        g_rowptr[i + 1] = v;
        g_wptr[i] = v - g_cnt[i];
    }
    if (i == 0) g_rowptr[0] = 0;
}
__global__ void scatter_kernel(const int* __restrict__ src,
                               const int* __restrict__ dst, int E) {
    int i = blockIdx.x * blockDim.x + threadIdx.x;
    if (i < E) {
        int pos = atomicAdd(&g_wptr[dst[i]], 1);
        g_col[pos] = src[i];
    }
}
__global__ void convW_kernel(const float* __restrict__ W1l, const float* __restrict__ W1r,
                             const float* __restrict__ W2l, const float* __restrict__ W2r) {
    int t = blockIdx.x * blockDim.x + threadIdx.x;
    if (t >= 2 * 256 * 512) return;
    int layer = t >> 17;
    int rem = t & 131071;
    int n = rem >> 9;
    int k = rem & 511;
    const float* Wl = layer ? W2l : W1l;
    const float* Wr = layer ? W2r : W1r;
    float v = (k < 256) ? Wl[k * 256 + n] : Wr[(k - 256) * 256 + n];
    __nv_bfloat16 h = __float2bfloat16_rn(v);
    g_Bhi[t] = h;
    g_Blo[t] = __float2bfloat16_rn(v - __bfloat162float(h));
}

// ---------------- aggregation (device body; warp per node) ----------------
__device__ __forceinline__ void agg_body(const float* __restrict__ x, int warp, int lane, int N) {
    if (warp >= N) return;
    int beg = g_rowptr[warp], end = g_rowptr[warp + 1];
    float4 a0 = make_float4(0.f, 0.f, 0.f, 0.f);
    float4 a1 = make_float4(0.f, 0.f, 0.f, 0.f);
    for (int j = beg; j < end; j++) {
        const float4* row = (const float4*)(x + (size_t)g_col[j] * D256);
        float4 v0 = row[lane], v1 = row[lane + 32];
        a0.x += v0.x; a0.y += v0.y; a0.z += v0.z; a0.w += v0.w;
        a1.x += v1.x; a1.y += v1.y; a1.z += v1.z; a1.w += v1.w;
    }
    int deg = end - beg;
    float sc = 1.0f / (float)(deg > 1 ? deg : 1);
    a0.x *= sc; a0.y *= sc; a0.z *= sc; a0.w *= sc;
    a1.x *= sc; a1.y *= sc; a1.z *= sc; a1.w *= sc;
    float h0 = bf_hi(a0.x), h1 = bf_hi(a0.y), h2 = bf_hi(a0.z), h3 = bf_hi(a0.w);
    float h4 = bf_hi(a1.x), h5 = bf_hi(a1.y), h6 = bf_hi(a1.z), h7 = bf_hi(a1.w);
    uint2* mh = (uint2*)g_mhi + (size_t)warp * 64;
    uint2* ml = (uint2*)g_mlo + (size_t)warp * 64;
    mh[lane]      = make_uint2(pk(h0, h1), pk(h2, h3));
    mh[lane + 32] = make_uint2(pk(h4, h5), pk(h6, h7));
    ml[lane]      = make_uint2(pk(a0.x - h0, a0.y - h1), pk(a0.z - h2, a0.w - h3));
    ml[lane + 32] = make_uint2(pk(a1.x - h4, a1.y - h5), pk(a1.z - h6, a1.w - h7));
}

// ---------------- half-GEMM body (K=256, split-bf16 3-term) ----------------
// CTA tile 128x128, 8 warps (warp tile 32x64). 8 K-chunks of 32.
// 2-stage cp.async pipeline, ONE __syncthreads per chunk.
#define ROWB 80
#define STAGEB 40960
#define SM_GEMM (2 * STAGEB + 512)

template<bool LPART, bool WRITE_HILO>
__device__ __forceinline__ void gemm_half_body(
    const __nv_bfloat16* __restrict__ Ahi_, const __nv_bfloat16* __restrict__ Alo_,
    const __nv_bfloat16* __restrict__ Bh_, const __nv_bfloat16* __restrict__ Bl_,
    int koff, const float* __restrict__ bias, const float* __restrict__ Cprev,
    float* __restrict__ Cf, __nv_bfloat16* __restrict__ Chi, __nv_bfloat16* __restrict__ Clo,
    int M, int gemm_bid, char* smem)
{
    uint32_t sb = smem_u32(smem);
    int tid = threadIdx.x;
    int wid = tid >> 5, lane = tid & 31;
    int wm = wid >> 1, wn = wid & 1;
    int qr = lane >> 2, qc = (lane & 3) * 2;
    int lr = lane & 7, lg = lane >> 3;
    int bm = (gemm_bid >> 1) * 128;
    int bn = (gemm_bid & 1) * 128;

    float* sbias = (float*)(smem + 2 * STAGEB);
    if (LPART) { if (tid < 128) sbias[tid] = bias[bn + tid]; }

    float acc[2][8][4];
#pragma unroll
    for (int i = 0; i < 2; i++)
#pragma unroll
        for (int j = 0; j < 8; j++)
#pragma unroll
            for (int v = 0; v < 4; v++) acc[i][j][v] = 0.f;

    auto issue_chunk = [&](int c, int stage) {
        int kl = c * 32;
        int k0 = koff + c * 32;
        uint32_t sbase = sb + stage * STAGEB;
#pragma unroll
        for (int it = 0; it < 8; it++) {
            int item = it * 256 + tid;
            int arr = item >> 9, rem = item & 511, r = rem >> 2, kg = rem & 3;
            uint32_t dst = sbase + arr * 10240 + r * ROWB + kg * 16;
            const __nv_bfloat16* src;
            if (arr < 2) {
                int ar = bm + r; if (ar >= M) ar = M - 1;
                src = (arr == 0 ? Ahi_ : Alo_) + (size_t)ar * 256 + kl + kg * 8;
            } else {
                src = (arr == 2 ? Bh_ : Bl_) + (size_t)(bn + r) * 512 + k0 + kg * 8;
            }
            CP_ASYNC16(dst, src);
        }
        CP_COMMIT();
    };

    issue_chunk(0, 0);
    for (int c = 0; c < 8; c++) {
        CP_WAIT0();
        __syncthreads();
        if (c < 7) issue_chunk(c + 1, (c + 1) & 1);
        int st = c & 1;
        uint32_t Ahb = sb + st * STAGEB;
        uint32_t Alb = Ahb + 10240;
        uint32_t Bhb = Ahb + 20480;
        uint32_t Blb = Ahb + 30720;
        int arow0 = wm * 32 + lr + ((lg & 1) << 3);
        int brow0 = wn * 64 + lr + ((lg >> 1) << 3);
#pragma unroll
        for (int k16 = 0; k16 < 32; k16 += 16) {
            uint32_t akofs = (uint32_t)((k16 + ((lg >> 1) << 3)) * 2);
            uint32_t bkofs = (uint32_t)((k16 + ((lg & 1) << 3)) * 2);
            uint32_t ah[2][4], al[2][4];
            ldsm_x4(ah[0], Ahb + arow0 * ROWB + akofs);
            ldsm_x4(ah[1], Ahb + (arow0 + 16) * ROWB + akofs);
            ldsm_x4(al[0], Alb + arow0 * ROWB + akofs);
            ldsm_x4(al[1], Alb + (arow0 + 16) * ROWB + akofs);
#pragma unroll
            for (int p = 0; p < 4; p++) {
                uint32_t bh[4], bl[4];
                ldsm_x4(bh, Bhb + (brow0 + p * 16) * ROWB + bkofs);
                ldsm_x4(bl, Blb + (brow0 + p * 16) * ROWB + bkofs);
#pragma unroll
                for (int mt = 0; mt < 2; mt++) {
#pragma unroll
                    for (int j = 0; j < 2; j++) {
                        float* a_ = acc[mt][p * 2 + j];
                        mma_bf16(a_, ah[mt], &bh[2 * j]);
                        mma_bf16(a_, ah[mt], &bl[2 * j]);
                        mma_bf16(a_, al[mt], &bh[2 * j]);
                    }
                }
            }
        }
        __syncthreads();
    }

    // --- epilogue ---
#pragma unroll
    for (int mt = 0; mt < 2; mt++) {
        int r0 = bm + wm * 32 + mt * 16 + qr;
#pragma unroll
        for (int nt = 0; nt < 8; nt++) {
            int lc = wn * 64 + nt * 8 + qc;
            int col = bn + lc;
            float v00 = acc[mt][nt][0], v01 = acc[mt][nt][1];
            float v10 = acc[mt][nt][2], v11 = acc[mt][nt][3];
            if (LPART) {
                float b0 = sbias[lc], b1 = sbias[lc + 1];
                v00 += b0; v01 += b1; v10 += b0; v11 += b1;
                if (r0 < M) {
                    float2 p0 = *(const float2*)&Cprev[(size_t)r0 * 256 + col];
                    v00 += p0.x; v01 += p0.y;
                }
                if (r0 + 8 < M) {
                    float2 p1 = *(const float2*)&Cprev[(size_t)(r0 + 8) * 256 + col];
                    v10 += p1.x; v11 += p1.y;
                }
            }
            if (r0 < M)
                *(float2*)&Cf[(size_t)r0 * 256 + col] = make_float2(v00, v01);
            if (r0 + 8 < M)
                *(float2*)&Cf[(size_t)(r0 + 8) * 256 + col] = make_float2(v10, v11);
            if (WRITE_HILO) {
                if (r0 < M) {
                    float h0 = bf_hi(v00), h1 = bf_hi(v01);
                    ((uint32_t*)Chi)[((size_t)r0 * 256 + col) >> 1] = pk(h0, h1);
                    ((uint32_t*)Clo)[((size_t)r0 * 256 + col) >> 1] = pk(v00 - h0, v01 - h1);
                }
                if (r0 + 8 < M) {
                    float h0 = bf_hi(v10), h1 = bf_hi(v11);
                    ((uint32_t*)Chi)[((size_t)(r0 + 8) * 256 + col) >> 1] = pk(h0, h1);
                    ((uint32_t*)Clo)[((size_t)(r0 + 8) * 256 + col) >> 1] = pk(v10 - h0, v11 - h1);
                }
            }
        }
    }
}

// fused: blocks [0, gemm_blks) do r-GEMM (A@Wr -> Cr); rest do aggregation of xagg
__global__ void __launch_bounds__(256, 2)
fused_r_agg_kernel(const __nv_bfloat16* __restrict__ Ahi, const __nv_bfloat16* __restrict__ Alo,
                   const __nv_bfloat16* __restrict__ Bh, const __nv_bfloat16* __restrict__ Bl,
                   float* __restrict__ Cr, const float* __restrict__ xagg,
                   int M, int gemm_blks) {
    extern __shared__ char smem[];
    if ((int)blockIdx.x < gemm_blks) {
        gemm_half_body<false, false>(Ahi, Alo, Bh, Bl, 256, nullptr, nullptr,
                                     Cr, nullptr, nullptr, M, blockIdx.x, smem);
    } else {
        int warp = (((int)blockIdx.x - gemm_blks) << 3) + (threadIdx.x >> 5);
        agg_body(xagg, warp, threadIdx.x & 31, M);
    }
}

template<bool WRITE_HILO>
__global__ void __launch_bounds__(256, 2)
gemm_l_kernel(const __nv_bfloat16* __restrict__ Ahi, const __nv_bfloat16* __restrict__ Alo,
              const __nv_bfloat16* __restrict__ Bh, const __nv_bfloat16* __restrict__ Bl,
              const float* __restrict__ bias, const float* __restrict__ Cprev,
              float* __restrict__ Cf, __nv_bfloat16* __restrict__ Chi,
              __nv_bfloat16* __restrict__ Clo, int M) {
    extern __shared__ char smem[];
    gemm_half_body<true, WRITE_HILO>(Ahi, Alo, Bh, Bl, 0, bias, Cprev,
                                     Cf, Chi, Clo, M, blockIdx.x, smem);
}

__global__ void gather_out_kernel(const float* __restrict__ xf,
                                  const int* __restrict__ idxA, int nA,
                                  const int* __restrict__ idxB,
                                  float* __restrict__ out) {
    int r = blockIdx.x;
    int srow = (r < nA) ? idxA[r] : idxB[r - nA];
    ((float4*)(out + (size_t)r * D256))[threadIdx.x] =
        ((const float4*)(xf + (size_t)srow * D256))[threadIdx.x];
}

extern "C" void kernel_launch(void* const* d_in, const int* in_sizes, int n_in,
                              void* d_out, int out_size) {
    const float* emb = (const float*)d_in[0];
    const float* W1l = (const float*)d_in[1];
    const float* b1l = (const float*)d_in[2];
    const float* W1r = (const float*)d_in[3];
    const float* W2l = (const float*)d_in[4];
    const float* b2l = (const float*)d_in[5];
    const float* W2r = (const float*)d_in[6];
    const int* x_idx = (const int*)d_in[7];
    const int* edge  = (const int*)d_in[8];
    const int* drug  = (const int*)d_in[9];
    const int* se    = (const int*)d_in[10];

    int N = in_sizes[7];
    int E = in_sizes[8] / 2;
    const int* src = edge;
    const int* dst = edge + E;
    int nd = in_sizes[9];
    int ns = in_sizes[10];

    float* out   = (float*)d_out;
    float* out_x = out + (size_t)(nd + ns) * D256;

    float *px, *ph, *pcr;
    __nv_bfloat16 *pxhi, *pxlo, *phhi, *phlo, *pmhi, *pmlo, *pbh, *pbl;
    cudaGetSymbolAddress((void**)&px, g_x);
    cudaGetSymbolAddress((void**)&ph, g_h);
    cudaGetSymbolAddress((void**)&pcr, g_cr);
    cudaGetSymbolAddress((void**)&pxhi, g_xhi);
    cudaGetSymbolAddress((void**)&pxlo, g_xlo);
    cudaGetSymbolAddress((void**)&phhi, g_hhi);
    cudaGetSymbolAddress((void**)&phlo, g_hlo);
    cudaGetSymbolAddress((void**)&pmhi, g_mhi);
    cudaGetSymbolAddress((void**)&pmlo, g_mlo);
    cudaGetSymbolAddress((void**)&pbh, g_Bhi);
    cudaGetSymbolAddress((void**)&pbl, g_Blo);

    static bool attr_set = false;
    if (!attr_set) {
        cudaFuncSetAttribute(fused_r_agg_kernel,
                             cudaFuncAttributeMaxDynamicSharedMemorySize, SM_GEMM);
        cudaFuncSetAttribute(gemm_l_kernel<true>,
                             cudaFuncAttributeMaxDynamicSharedMemorySize, SM_GEMM);
        cudaFuncSetAttribute(gemm_l_kernel<false>,
                             cudaFuncAttributeMaxDynamicSharedMemorySize, SM_GEMM);
        attr_set = true;
    }

    int nb = (N + SCAN_BLK - 1) / SCAN_BLK;
    int gemm_blks = 2 * ((N + 127) / 128);
    int agg_blks = (N + 7) / 8;

    // --- CSR build + input gather + weight conversion ---
    zero_cnt_kernel<<<(N + 255) / 256, 256>>>(N);
    gather_x_kernel<<<(N * 32 + 255) / 256, 256>>>(emb, x_idx, N);
    convW_kernel<<<(2 * 256 * 512 + 255) / 256, 256>>>(W1l, W1r, W2l, W2r);
    hist_kernel<<<(E + 255) / 256, 256>>>(dst, E);
    scan_local_kernel<<<nb, SCAN_BLK>>>(N);
    scan_part_kernel<<<1, 1>>>(nb);
    scan_final_kernel<<<nb, SCAN_BLK>>>(N);
    scatter_kernel<<<(E + 255) / 256, 256>>>(src, dst, E);

    // --- layer 1: [r-GEMM(x@W1r) || agg(x)] then l-GEMM(mean@W1l + b + Cr -> h) ---
    fused_r_agg_kernel<<<gemm_blks + agg_blks, 256, SM_GEMM>>>(
        pxhi, pxlo, pbh, pbl, pcr, px, N, gemm_blks);
    gemm_l_kernel<true><<<gemm_blks, 256, SM_GEMM>>>(
        pmhi, pmlo, pbh, pbl, b1l, pcr, ph, phhi, phlo, N);

    // --- layer 2: [r-GEMM(h@W2r) || agg(h)] then l-GEMM -> out_x ---
    fused_r_agg_kernel<<<gemm_blks + agg_blks, 256, SM_GEMM>>>(
        phhi, phlo, pbh + 256 * 512, pbl + 256 * 512, pcr, ph, N, gemm_blks);
    gemm_l_kernel<false><<<gemm_blks, 256, SM_GEMM>>>(
        pmhi, pmlo, pbh + 256 * 512, pbl + 256 * 512, b2l, pcr, out_x,
        nullptr, nullptr, N);

    // --- output gathers ---
    gather_out_kernel<<<nd + ns, 64>>>(out_x, drug, nd, se, out);
}

// round 6
// speedup vs baseline: 1.0841x; 1.0841x over previous
#include <cuda_runtime.h>
#include <cuda_bf16.h>
#include <cstdint>

#define D256 256
#define NMAX 100000
#define EMAX 1600000
#define SCAN_BLK 1024

// ---------------- scratch (device globals) ----------------
__device__ float g_x[(size_t)NMAX * D256];      // fp32 x (for aggregation L1)
__device__ float g_h[(size_t)NMAX * D256];      // fp32 h (for aggregation L2)
__device__ __nv_bfloat16 g_xhi[(size_t)NMAX * D256];
__device__ __nv_bfloat16 g_xlo[(size_t)NMAX * D256];
__device__ __nv_bfloat16 g_hhi[(size_t)NMAX * D256];
__device__ __nv_bfloat16 g_hlo[(size_t)NMAX * D256];
__device__ __nv_bfloat16 g_mhi[(size_t)NMAX * D256];
__device__ __nv_bfloat16 g_mlo[(size_t)NMAX * D256];
__device__ int   g_cnt[NMAX + 1];
__device__ int   g_incl[NMAX + 1];
__device__ int   g_rowptr[NMAX + 2];
__device__ int   g_wptr[NMAX + 1];
__device__ int   g_col[EMAX];
__device__ int   g_part[256];
__device__ int   g_poff[256];
// pre-converted weights: [layer][n (256)][k (512)] bf16 hi/lo
__device__ __nv_bfloat16 g_Bhi[2 * 256 * 512];
__device__ __nv_bfloat16 g_Blo[2 * 256 * 512];

// ---------------- helpers ----------------
__device__ __forceinline__ float bf_hi(float v) {
    return __bfloat162float(__float2bfloat16_rn(v));
}
__device__ __forceinline__ uint32_t pk(float a, float b) {
    uint32_t lo = __bfloat16_as_ushort(__float2bfloat16_rn(a));
    uint32_t hi = __bfloat16_as_ushort(__float2bfloat16_rn(b));
    return lo | (hi << 16);
}
__device__ __forceinline__ uint32_t smem_u32(const void* p) {
    uint32_t a;
    asm("{ .reg .u64 t; cvta.to.shared.u64 t, %1; cvt.u32.u64 %0, t; }"
        : "=r"(a) : "l"(p));
    return a;
}
__device__ __forceinline__ void mma_bf16(float* c, const uint32_t* a, const uint32_t* b) {
    asm volatile(
        "mma.sync.aligned.m16n8k16.row.col.f32.bf16.bf16.f32 "
        "{%0,%1,%2,%3}, {%4,%5,%6,%7}, {%8,%9}, {%0,%1,%2,%3};"
        : "+f"(c[0]), "+f"(c[1]), "+f"(c[2]), "+f"(c[3])
        : "r"(a[0]), "r"(a[1]), "r"(a[2]), "r"(a[3]), "r"(b[0]), "r"(b[1]));
}
__device__ __forceinline__ void ldsm_x4(uint32_t* r, uint32_t addr) {
    asm volatile("ldmatrix.sync.aligned.m8n8.x4.shared.b16 {%0,%1,%2,%3}, [%4];"
                 : "=r"(r[0]), "=r"(r[1]), "=r"(r[2]), "=r"(r[3]) : "r"(addr));
}
#define CP_ASYNC16(dst, src) asm volatile( \
    "cp.async.cg.shared.global [%0], [%1], 16;" :: "r"(dst), "l"(src) : "memory")
#define CP_COMMIT() asm volatile("cp.async.commit_group;" ::: "memory")

// ---------------- small utility kernels ----------------
__global__ void zero_cnt_kernel(int n) {
    int i = blockIdx.x * blockDim.x + threadIdx.x;
    if (i < n) g_cnt[i] = 0;
}
__global__ void gather_x_kernel(const float* __restrict__ emb,
                                const int* __restrict__ idx, int N) {
    int t = blockIdx.x * blockDim.x + threadIdx.x;
    if (t >= N * 32) return;
    int r = t >> 5, c = t & 31;
    const float4* p = (const float4*)emb + (size_t)idx[r] * 64 + c * 2;
    float4 v0 = p[0], v1 = p[1];
    size_t eo = (size_t)r * 64 + c * 2;
    ((float4*)g_x)[eo] = v0;
    ((float4*)g_x)[eo + 1] = v1;
    float h0 = bf_hi(v0.x), h1 = bf_hi(v0.y), h2 = bf_hi(v0.z), h3 = bf_hi(v0.w);
    float h4 = bf_hi(v1.x), h5 = bf_hi(v1.y), h6 = bf_hi(v1.z), h7 = bf_hi(v1.w);
    ((uint4*)g_xhi)[(size_t)r * 32 + c] =
        make_uint4(pk(h0, h1), pk(h2, h3), pk(h4, h5), pk(h6, h7));
    ((uint4*)g_xlo)[(size_t)r * 32 + c] =
        make_uint4(pk(v0.x - h0, v0.y - h1), pk(v0.z - h2, v0.w - h3),
                   pk(v1.x - h4, v1.y - h5), pk(v1.z - h6, v1.w - h7));
}
__global__ void hist_kernel(const int* __restrict__ dst, int E) {
    int i = blockIdx.x * blockDim.x + threadIdx.x;
    if (i < E) atomicAdd(&g_cnt[dst[i]], 1);
}
__global__ void scan_local_kernel(int N) {
    __shared__ int s[SCAN_BLK];
    int i = blockIdx.x * SCAN_BLK + threadIdx.x;
    int v = (i < N) ? g_cnt[i] : 0;
    s[threadIdx.x] = v;
    __syncthreads();
    for (int off = 1; off < SCAN_BLK; off <<= 1) {
        int t = (threadIdx.x >= off) ? s[threadIdx.x - off] : 0;
        __syncthreads();
        s[threadIdx.x] += t;
        __syncthreads();
    }
    if (i < N) g_incl[i] = s[threadIdx.x];
    if (threadIdx.x == SCAN_BLK - 1) g_part[blockIdx.x] = s[SCAN_BLK - 1];
}
__global__ void scan_part_kernel(int nb) {
    int run = 0;
    for (int b = 0; b < nb; b++) { g_poff[b] = run; run += g_part[b]; }
}
__global__ void scan_final_kernel(int N) {
    int i = blockIdx.x * SCAN_BLK + threadIdx.x;
    if (i < N) {
        int v = g_incl[i] + g_poff[blockIdx.x];
        g_rowptr[i + 1] = v;
        g_wptr[i] = v - g_cnt[i];
    }
    if (i == 0) g_rowptr[0] = 0;
}
__global__ void scatter_kernel(const int* __restrict__ src,
                               const int* __restrict__ dst, int E) {
    int i = blockIdx.x * blockDim.x + threadIdx.x;
    if (i < E) {
        int pos = atomicAdd(&g_wptr[dst[i]], 1);
        g_col[pos] = src[i];
    }
}
// mean aggregation: reads fp32 x, writes bf16 hi/lo mean (GEMM is sole consumer)
__global__ void aggregate_kernel(const float* __restrict__ x, int N) {
    int warp = (blockIdx.x * blockDim.x + threadIdx.x) >> 5;
    int lane = threadIdx.x & 31;
    if (warp >= N) return;
    int beg = g_rowptr[warp], end = g_rowptr[warp + 1];
    float4 a0 = make_float4(0.f, 0.f, 0.f, 0.f);
    float4 a1 = make_float4(0.f, 0.f, 0.f, 0.f);
    for (int j = beg; j < end; j++) {
        const float4* row = (const float4*)(x + (size_t)g_col[j] * D256);
        float4 v0 = row[lane], v1 = row[lane + 32];
        a0.x += v0.x; a0.y += v0.y; a0.z += v0.z; a0.w += v0.w;
        a1.x += v1.x; a1.y += v1.y; a1.z += v1.z; a1.w += v1.w;
    }
    int deg = end - beg;
    float sc = 1.0f / (float)(deg > 1 ? deg : 1);
    a0.x *= sc; a0.y *= sc; a0.z *= sc; a0.w *= sc;
    a1.x *= sc; a1.y *= sc; a1.z *= sc; a1.w *= sc;
    float h0 = bf_hi(a0.x), h1 = bf_hi(a0.y), h2 = bf_hi(a0.z), h3 = bf_hi(a0.w);
    float h4 = bf_hi(a1.x), h5 = bf_hi(a1.y), h6 = bf_hi(a1.z), h7 = bf_hi(a1.w);
    uint2* mh = (uint2*)g_mhi + (size_t)warp * 64;
    uint2* ml = (uint2*)g_mlo + (size_t)warp * 64;
    mh[lane]      = make_uint2(pk(h0, h1), pk(h2, h3));
    mh[lane + 32] = make_uint2(pk(h4, h5), pk(h6, h7));
    ml[lane]      = make_uint2(pk(a0.x - h0, a0.y - h1), pk(a0.z - h2, a0.w - h3));
    ml[lane + 32] = make_uint2(pk(a1.x - h4, a1.y - h5), pk(a1.z - h6, a1.w - h7));
}
__global__ void convW_kernel(const float* __restrict__ W1l, const float* __restrict__ W1r,
                             const float* __restrict__ W2l, const float* __restrict__ W2r) {
    int t = blockIdx.x * blockDim.x + threadIdx.x;
    if (t >= 2 * 256 * 512) return;
    int layer = t >> 17;
    int rem = t & 131071;
    int n = rem >> 9;
    int k = rem & 511;
    const float* Wl = layer ? W2l : W1l;
    const float* Wr = layer ? W2r : W1r;
    float v = (k < 256) ? Wl[k * 256 + n] : Wr[(k - 256) * 256 + n];
    __nv_bfloat16 h = __float2bfloat16_rn(v);
    g_Bhi[t] = h;
    g_Blo[t] = __float2bfloat16_rn(v - __bfloat162float(h));
}

// ---------------- pipelined mma.sync GEMM, CTA tile 128x256, warp tile 64x64 ----
// C[M,256] = Am@Wl + Ax@Wr + bias, split-bf16 3-term.
// 8 warps in 2x4 (wm=wid>>2 row-64 group, wn=wid&3 col-64 group).
// K: 16 chunks of 32 (8 Am, 8 Ax). 2-stage cp.async pipeline (R4-proven 2-sync loop).
// stage: Ahi 10240 + Alo 10240 + Bhi 20480 + Blo 20480 = 61440B; x2 + bias = 123904B.
#define ROWB 80
#define STAGEB 61440
#define SM_GEMM (2 * STAGEB + 1024)

__global__ void __launch_bounds__(256, 1)
gemm_mma_kernel(const __nv_bfloat16* __restrict__ Amhi, const __nv_bfloat16* __restrict__ Amlo,
                const __nv_bfloat16* __restrict__ Axhi, const __nv_bfloat16* __restrict__ Axlo,
                const __nv_bfloat16* __restrict__ Bhi, const __nv_bfloat16* __restrict__ Blo,
                const float* __restrict__ bias, float* __restrict__ Cf,
                __nv_bfloat16* __restrict__ Chi, __nv_bfloat16* __restrict__ Clo, int M) {
    extern __shared__ char smem[];
    uint32_t sb = smem_u32(smem);
    int tid = threadIdx.x;
    int wid = tid >> 5, lane = tid & 31;
    int wm = wid >> 2, wn = wid & 3;
    int qr = lane >> 2, qc = (lane & 3) * 2;
    int lr = lane & 7, lg = lane >> 3;
    int bm = blockIdx.x * 128;

    float* sbias = (float*)(smem + 2 * STAGEB);
    if (tid < 256) sbias[tid] = bias[tid];

    float acc[4][8][4];
#pragma unroll
    for (int i = 0; i < 4; i++)
#pragma unroll
        for (int j = 0; j < 8; j++)
#pragma unroll
            for (int v = 0; v < 4; v++) acc[i][j][v] = 0.f;

    // fill-chunk: A 128x32 hi/lo (512+512 x16B) + B 256x32 hi/lo (1024+1024 x16B)
    auto issue_chunk = [&](int c, int stage) {
        const __nv_bfloat16* Ah = (c < 8) ? Amhi : Axhi;
        const __nv_bfloat16* Al = (c < 8) ? Amlo : Axlo;
        int kl = (c & 7) * 32;
        int k0 = c * 32;
        uint32_t sbase = sb + stage * STAGEB;
#pragma unroll
        for (int it = 0; it < 12; it++) {
            int item = it * 256 + tid;          // 0..3071
            uint32_t dst;
            const __nv_bfloat16* src;
            if (item < 1024) {                  // A hi (0..511), A lo (512..1023)
                int arr = item >> 9, rem = item & 511, r = rem >> 2, kg = rem & 3;
                int ar = bm + r; if (ar >= M) ar = M - 1;
                dst = sbase + arr * 10240 + r * ROWB + kg * 16;
                src = (arr == 0 ? Ah : Al) + (size_t)ar * 256 + kl + kg * 8;
            } else {                            // B hi (0..1023), B lo (1024..2047)
                int itb = item - 1024;
                int arr = itb >> 10, rem = itb & 1023, n = rem >> 2, kg = rem & 3;
                dst = sbase + 20480 + arr * 20480 + n * ROWB + kg * 16;
                src = (arr == 0 ? Bhi : Blo) + (size_t)n * 512 + k0 + kg * 8;
            }
            CP_ASYNC16(dst, src);
        }
        CP_COMMIT();
    };

    issue_chunk(0, 0);
    for (int c = 0; c < 16; c++) {
        int st = c & 1;
        if (c < 15) {
            issue_chunk(c + 1, st ^ 1);
            asm volatile("cp.async.wait_group 1;" ::: "memory");
        } else {
            asm volatile("cp.async.wait_group 0;" ::: "memory");
        }
        __syncthreads();

        uint32_t Ahb = sb + st * STAGEB;
        uint32_t Alb = Ahb + 10240;
        uint32_t Bhb = Ahb + 20480;
        uint32_t Blb = Ahb + 40960;
        int arow0 = wm * 64 + lr + ((lg & 1) << 3);
        int brow0 = wn * 64 + lr + ((lg >> 1) << 3);
#pragma unroll
        for (int k16 = 0; k16 < 32; k16 += 16) {
            uint32_t akofs = (uint32_t)((k16 + ((lg >> 1) << 3)) * 2);
            uint32_t bkofs = (uint32_t)((k16 + ((lg & 1) << 3)) * 2);
            uint32_t ah[4][4], al[4][4];
#pragma unroll
            for (int mt = 0; mt < 4; mt++) {
                ldsm_x4(ah[mt], Ahb + (arow0 + mt * 16) * ROWB + akofs);
                ldsm_x4(al[mt], Alb + (arow0 + mt * 16) * ROWB + akofs);
            }
#pragma unroll
            for (int p = 0; p < 4; p++) {
                uint32_t bh[4], bl[4];
                ldsm_x4(bh, Bhb + (brow0 + p * 16) * ROWB + bkofs);
                ldsm_x4(bl, Blb + (brow0 + p * 16) * ROWB + bkofs);
#pragma unroll
                for (int mt = 0; mt < 4; mt++) {
#pragma unroll
                    for (int j = 0; j < 2; j++) {
                        float* a_ = acc[mt][p * 2 + j];
                        mma_bf16(a_, ah[mt], &bh[2 * j]);
                        mma_bf16(a_, ah[mt], &bl[2 * j]);
                        mma_bf16(a_, al[mt], &bh[2 * j]);
                    }
                }
            }
        }
        __syncthreads();
    }

    // --- epilogue ---
#pragma unroll
    for (int mt = 0; mt < 4; mt++) {
        int r0 = bm + wm * 64 + mt * 16 + qr;
#pragma unroll
        for (int nt = 0; nt < 8; nt++) {
            int col = wn * 64 + nt * 8 + qc;
            float b0 = sbias[col], b1 = sbias[col + 1];
            float v00 = acc[mt][nt][0] + b0, v01 = acc[mt][nt][1] + b1;
            float v10 = acc[mt][nt][2] + b0, v11 = acc[mt][nt][3] + b1;
            if (r0 < M)
                *(float2*)&Cf[(size_t)r0 * 256 + col] = make_float2(v00, v01);
            if (r0 + 8 < M)
                *(float2*)&Cf[(size_t)(r0 + 8) * 256 + col] = make_float2(v10, v11);
            if (Chi) {
                if (r0 < M) {
                    float h0 = bf_hi(v00), h1 = bf_hi(v01);
                    ((uint32_t*)Chi)[((size_t)r0 * 256 + col) >> 1] = pk(h0, h1);
                    ((uint32_t*)Clo)[((size_t)r0 * 256 + col) >> 1] = pk(v00 - h0, v01 - h1);
                }
                if (r0 + 8 < M) {
                    float h0 = bf_hi(v10), h1 = bf_hi(v11);
                    ((uint32_t*)Chi)[((size_t)(r0 + 8) * 256 + col) >> 1] = pk(h0, h1);
                    ((uint32_t*)Clo)[((size_t)(r0 + 8) * 256 + col) >> 1] = pk(v10 - h0, v11 - h1);
                }
            }
        }
    }
}

__global__ void gather_out_kernel(const float* __restrict__ xf,
                                  const int* __restrict__ idxA, int nA,
                                  const int* __restrict__ idxB,
                                  float* __restrict__ out) {
    int r = blockIdx.x;
    int srow = (r < nA) ? idxA[r] : idxB[r - nA];
    ((float4*)(out + (size_t)r * D256))[threadIdx.x] =
        ((const float4*)(xf + (size_t)srow * D256))[threadIdx.x];
}

extern "C" void kernel_launch(void* const* d_in, const int* in_sizes, int n_in,
                              void* d_out, int out_size) {
    const float* emb = (const float*)d_in[0];
    const float* W1l = (const float*)d_in[1];
    const float* b1l = (const float*)d_in[2];
    const float* W1r = (const float*)d_in[3];
    const float* W2l = (const float*)d_in[4];
    const float* b2l = (const float*)d_in[5];
    const float* W2r = (const float*)d_in[6];
    const int* x_idx = (const int*)d_in[7];
    const int* edge  = (const int*)d_in[8];
    const int* drug  = (const int*)d_in[9];
    const int* se    = (const int*)d_in[10];

    int N = in_sizes[7];
    int E = in_sizes[8] / 2;
    const int* src = edge;
    const int* dst = edge + E;
    int nd = in_sizes[9];
    int ns = in_sizes[10];

    float* out   = (float*)d_out;
    float* out_x = out + (size_t)(nd + ns) * D256;

    float *px, *ph;
    __nv_bfloat16 *pxhi, *pxlo, *phhi, *phlo, *pmhi, *pmlo, *pbh, *pbl;
    cudaGetSymbolAddress((void**)&px, g_x);
    cudaGetSymbolAddress((void**)&ph, g_h);
    cudaGetSymbolAddress((void**)&pxhi, g_xhi);
    cudaGetSymbolAddress((void**)&pxlo, g_xlo);
    cudaGetSymbolAddress((void**)&phhi, g_hhi);
    cudaGetSymbolAddress((void**)&phlo, g_hlo);
    cudaGetSymbolAddress((void**)&pmhi, g_mhi);
    cudaGetSymbolAddress((void**)&pmlo, g_mlo);
    cudaGetSymbolAddress((void**)&pbh, g_Bhi);
    cudaGetSymbolAddress((void**)&pbl, g_Blo);

    static bool attr_set = false;
    if (!attr_set) {
        cudaFuncSetAttribute(gemm_mma_kernel,
                             cudaFuncAttributeMaxDynamicSharedMemorySize, SM_GEMM);
        attr_set = true;
    }

    int nb = (N + SCAN_BLK - 1) / SCAN_BLK;
    int gblocks = (N + 127) / 128;

    // --- CSR build + input gather + weight conversion ---
    zero_cnt_kernel<<<(N + 255) / 256, 256>>>(N);
    gather_x_kernel<<<(N * 32 + 255) / 256, 256>>>(emb, x_idx, N);
    convW_kernel<<<(2 * 256 * 512 + 255) / 256, 256>>>(W1l, W1r, W2l, W2r);
    hist_kernel<<<(E + 255) / 256, 256>>>(dst, E);
    scan_local_kernel<<<nb, SCAN_BLK>>>(N);
    scan_part_kernel<<<1, 1>>>(nb);
    scan_final_kernel<<<nb, SCAN_BLK>>>(N);
    scatter_kernel<<<(E + 255) / 256, 256>>>(src, dst, E);

    // --- layer 1: agg(x) -> mean hi/lo ; GEMM -> h fp32 + hi/lo ---
    aggregate_kernel<<<(N * 32 + 255) / 256, 256>>>(px, N);
    gemm_mma_kernel<<<gblocks, 256, SM_GEMM>>>(pmhi, pmlo, pxhi, pxlo, pbh, pbl,
                                               b1l, ph, phhi, phlo, N);

    // --- layer 2: agg(h) -> mean hi/lo ; GEMM -> out_x fp32 ---
    aggregate_kernel<<<(N * 32 + 255) / 256, 256>>>(ph, N);
    gemm_mma_kernel<<<gblocks, 256, SM_GEMM>>>(pmhi, pmlo, phhi, phlo,
                                               pbh + 256 * 512, pbl + 256 * 512,
                                               b2l, out_x, nullptr, nullptr, N);

    // --- output gathers ---
    gather_out_kernel<<<nd + ns, 64>>>(out_x, drug, nd, se, out);
}

// round 7
// speedup vs baseline: 1.2100x; 1.1161x over previous
#include <cuda_runtime.h>
#include <cuda_bf16.h>
#include <cstdint>

#define D256 256
#define NMAX 100000
#define EMAX 1600000
#define SCAN_BLK 1024

// ---------------- scratch (device globals) ----------------
__device__ __nv_bfloat16 g_xhi[(size_t)NMAX * D256];
__device__ __nv_bfloat16 g_xlo[(size_t)NMAX * D256];
__device__ __nv_bfloat16 g_hhi[(size_t)NMAX * D256];
__device__ __nv_bfloat16 g_hlo[(size_t)NMAX * D256];
__device__ __nv_bfloat16 g_mhi[(size_t)NMAX * D256];
__device__ __nv_bfloat16 g_mlo[(size_t)NMAX * D256];
__device__ int   g_cnt[NMAX + 1];
__device__ int   g_incl[NMAX + 1];
__device__ int   g_rowptr[NMAX + 2];
__device__ int   g_wptr[NMAX + 1];
__device__ int   g_col[EMAX];
__device__ int   g_part[256];
__device__ int   g_poff[256];
// pre-converted weights: [layer][n (256)][k (512)] bf16 hi/lo
__device__ __nv_bfloat16 g_Bhi[2 * 256 * 512];
__device__ __nv_bfloat16 g_Blo[2 * 256 * 512];

// ---------------- helpers ----------------
__device__ __forceinline__ float bf_hi(float v) {
    return __bfloat162float(__float2bfloat16_rn(v));
}
__device__ __forceinline__ uint32_t pk(float a, float b) {
    uint32_t lo = __bfloat16_as_ushort(__float2bfloat16_rn(a));
    uint32_t hi = __bfloat16_as_ushort(__float2bfloat16_rn(b));
    return lo | (hi << 16);
}
__device__ __forceinline__ uint32_t smem_u32(const void* p) {
    uint32_t a;
    asm("{ .reg .u64 t; cvta.to.shared.u64 t, %1; cvt.u32.u64 %0, t; }"
        : "=r"(a) : "l"(p));
    return a;
}
__device__ __forceinline__ void mma_bf16(float* c, const uint32_t* a, const uint32_t* b) {
    asm volatile(
        "mma.sync.aligned.m16n8k16.row.col.f32.bf16.bf16.f32 "
        "{%0,%1,%2,%3}, {%4,%5,%6,%7}, {%8,%9}, {%0,%1,%2,%3};"
        : "+f"(c[0]), "+f"(c[1]), "+f"(c[2]), "+f"(c[3])
        : "r"(a[0]), "r"(a[1]), "r"(a[2]), "r"(a[3]), "r"(b[0]), "r"(b[1]));
}
__device__ __forceinline__ void ldsm_x4(uint32_t* r, uint32_t addr) {
    asm volatile("ldmatrix.sync.aligned.m8n8.x4.shared.b16 {%0,%1,%2,%3}, [%4];"
                 : "=r"(r[0]), "=r"(r[1]), "=r"(r[2]), "=r"(r[3]) : "r"(addr));
}
#define CP_ASYNC16(dst, src) asm volatile( \
    "cp.async.cg.shared.global [%0], [%1], 16;" :: "r"(dst), "l"(src) : "memory")
#define CP_COMMIT() asm volatile("cp.async.commit_group;" ::: "memory")

// accumulate both bf16 halves of packed word w (lo16 = even col, hi16 = odd col)
__device__ __forceinline__ void acc_pair(float& e, float& o, uint32_t w) {
    e += __uint_as_float(w << 16);
    o += __uint_as_float(w & 0xFFFF0000u);
}

// ---------------- small utility kernels ----------------
__global__ void zero_cnt_kernel(int n) {
    int i = blockIdx.x * blockDim.x + threadIdx.x;
    if (i < n) g_cnt[i] = 0;
}
// x = emb[x_idx]; writes ONLY hi/lo bf16 planes
__global__ void gather_x_kernel(const float* __restrict__ emb,
                                const int* __restrict__ idx, int N) {
    int t = blockIdx.x * blockDim.x + threadIdx.x;
    if (t >= N * 32) return;
    int r = t >> 5, c = t & 31;
    const float4* p = (const float4*)emb + (size_t)idx[r] * 64 + c * 2;
    float4 v0 = p[0], v1 = p[1];
    float h0 = bf_hi(v0.x), h1 = bf_hi(v0.y), h2 = bf_hi(v0.z), h3 = bf_hi(v0.w);
    float h4 = bf_hi(v1.x), h5 = bf_hi(v1.y), h6 = bf_hi(v1.z), h7 = bf_hi(v1.w);
    ((uint4*)g_xhi)[(size_t)r * 32 + c] =
        make_uint4(pk(h0, h1), pk(h2, h3), pk(h4, h5), pk(h6, h7));
    ((uint4*)g_xlo)[(size_t)r * 32 + c] =
        make_uint4(pk(v0.x - h0, v0.y - h1), pk(v0.z - h2, v0.w - h3),
                   pk(v1.x - h4, v1.y - h5), pk(v1.z - h6, v1.w - h7));
}
__global__ void hist_kernel(const int* __restrict__ dst, int E) {
    int i = blockIdx.x * blockDim.x + threadIdx.x;
    if (i < E) atomicAdd(&g_cnt[dst[i]], 1);
}
__global__ void scan_local_kernel(int N) {
    __shared__ int s[SCAN_BLK];
    int i = blockIdx.x * SCAN_BLK + threadIdx.x;
    int v = (i < N) ? g_cnt[i] : 0;
    s[threadIdx.x] = v;
    __syncthreads();
    for (int off = 1; off < SCAN_BLK; off <<= 1) {
        int t = (threadIdx.x >= off) ? s[threadIdx.x - off] : 0;
        __syncthreads();
        s[threadIdx.x] += t;
        __syncthreads();
    }
    if (i < N) g_incl[i] = s[threadIdx.x];
    if (threadIdx.x == SCAN_BLK - 1) g_part[blockIdx.x] = s[SCAN_BLK - 1];
}
__global__ void scan_part_kernel(int nb) {
    int run = 0;
    for (int b = 0; b < nb; b++) { g_poff[b] = run; run += g_part[b]; }
}
__global__ void scan_final_kernel(int N) {
    int i = blockIdx.x * SCAN_BLK + threadIdx.x;
    if (i < N) {
        int v = g_incl[i] + g_poff[blockIdx.x];
        g_rowptr[i + 1] = v;
        g_wptr[i] = v - g_cnt[i];
    }
    if (i == 0) g_rowptr[0] = 0;
}
__global__ void scatter_kernel(const int* __restrict__ src,
                               const int* __restrict__ dst, int E) {
    int i = blockIdx.x * blockDim.x + threadIdx.x;
    if (i < E) {
        int pos = atomicAdd(&g_wptr[dst[i]], 1);
        g_col[pos] = src[i];
    }
}
// mean aggregation: gathers hi/lo bf16 planes, reconstructs (hi+lo), writes mean hi/lo
__global__ void aggregate_kernel(const __nv_bfloat16* __restrict__ xhi,
                                 const __nv_bfloat16* __restrict__ xlo, int N) {
    int warp = (blockIdx.x * blockDim.x + threadIdx.x) >> 5;
    int lane = threadIdx.x & 31;
    if (warp >= N) return;
    int beg = g_rowptr[warp], end = g_rowptr[warp + 1];
    // lane owns cols 4*lane..+3 (acc a0) and 128+4*lane..+3 (acc a1)
    float4 a0 = make_float4(0.f, 0.f, 0.f, 0.f);
    float4 a1 = make_float4(0.f, 0.f, 0.f, 0.f);
    for (int j = beg; j < end; j++) {
        size_t s = (size_t)g_col[j];
        const uint2* rh = (const uint2*)(xhi + s * D256);
        const uint2* rl = (const uint2*)(xlo + s * D256);
        uint2 ha = rh[lane], hb = rh[lane + 32];
        uint2 la = rl[lane], lb = rl[lane + 32];
        acc_pair(a0.x, a0.y, ha.x); acc_pair(a0.z, a0.w, ha.y);
        acc_pair(a1.x, a1.y, hb.x); acc_pair(a1.z, a1.w, hb.y);
        acc_pair(a0.x, a0.y, la.x); acc_pair(a0.z, a0.w, la.y);
        acc_pair(a1.x, a1.y, lb.x); acc_pair(a1.z, a1.w, lb.y);
    }
    int deg = end - beg;
    float sc = 1.0f / (float)(deg > 1 ? deg : 1);
    a0.x *= sc; a0.y *= sc; a0.z *= sc; a0.w *= sc;
    a1.x *= sc; a1.y *= sc; a1.z *= sc; a1.w *= sc;
    float h0 = bf_hi(a0.x), h1 = bf_hi(a0.y), h2 = bf_hi(a0.z), h3 = bf_hi(a0.w);
    float h4 = bf_hi(a1.x), h5 = bf_hi(a1.y), h6 = bf_hi(a1.z), h7 = bf_hi(a1.w);
    uint2* mh = (uint2*)g_mhi + (size_t)warp * 64;
    uint2* ml = (uint2*)g_mlo + (size_t)warp * 64;
    mh[lane]      = make_uint2(pk(h0, h1), pk(h2, h3));
    mh[lane + 32] = make_uint2(pk(h4, h5), pk(h6, h7));
    ml[lane]      = make_uint2(pk(a0.x - h0, a0.y - h1), pk(a0.z - h2, a0.w - h3));
    ml[lane + 32] = make_uint2(pk(a1.x - h4, a1.y - h5), pk(a1.z - h6, a1.w - h7));
}
__global__ void convW_kernel(const float* __restrict__ W1l, const float* __restrict__ W1r,
                             const float* __restrict__ W2l, const float* __restrict__ W2r) {
    int t = blockIdx.x * blockDim.x + threadIdx.x;
    if (t >= 2 * 256 * 512) return;
    int layer = t >> 17;
    int rem = t & 131071;
    int n = rem >> 9;
    int k = rem & 511;
    const float* Wl = layer ? W2l : W1l;
    const float* Wr = layer ? W2r : W1r;
    float v = (k < 256) ? Wl[k * 256 + n] : Wr[(k - 256) * 256 + n];
    __nv_bfloat16 h = __float2bfloat16_rn(v);
    g_Bhi[t] = h;
    g_Blo[t] = __float2bfloat16_rn(v - __bfloat162float(h));
}

// ---------------- pipelined mma.sync GEMM (R4-proven config) ----------------
// C[M,256] = Am@Wl + Ax@Wr + bias, split-bf16 3-term; A pre-split hi/lo bf16.
// CTA 256 thr, tile 128x128; warp tile 32x64. K: 16 chunks of 32 (8 Am, 8 Ax).
// 2-stage cp.async pipeline; ldmatrix fragment loads; 2 CTAs/SM.
#define ROWB 80
#define STAGEB 40960
#define SM_GEMM (2 * STAGEB + 512)

__global__ void __launch_bounds__(256, 2)
gemm_mma_kernel(const __nv_bfloat16* __restrict__ Amhi, const __nv_bfloat16* __restrict__ Amlo,
                const __nv_bfloat16* __restrict__ Axhi, const __nv_bfloat16* __restrict__ Axlo,
                const __nv_bfloat16* __restrict__ Bhi, const __nv_bfloat16* __restrict__ Blo,
                const float* __restrict__ bias, float* __restrict__ Cf,
                __nv_bfloat16* __restrict__ Chi, __nv_bfloat16* __restrict__ Clo, int M) {
    extern __shared__ char smem[];
    uint32_t sb = smem_u32(smem);
    int tid = threadIdx.x;
    int wid = tid >> 5, lane = tid & 31;
    int wm = wid >> 1, wn = wid & 1;
    int qr = lane >> 2, qc = (lane & 3) * 2;
    int lr = lane & 7, lg = lane >> 3;
    int bm = blockIdx.y * 128;
    int bn = blockIdx.x * 128;

    float* sbias = (float*)(smem + 2 * STAGEB);
    if (tid < 128) sbias[tid] = bias[bn + tid];

    float acc[2][8][4];
#pragma unroll
    for (int i = 0; i < 2; i++)
#pragma unroll
        for (int j = 0; j < 8; j++)
#pragma unroll
            for (int v = 0; v < 4; v++) acc[i][j][v] = 0.f;

    auto issue_chunk = [&](int c, int stage) {
        const __nv_bfloat16* Ah = (c < 8) ? Amhi : Axhi;
        const __nv_bfloat16* Al = (c < 8) ? Amlo : Axlo;
        int kl = (c & 7) * 32;
        int k0 = c * 32;
        uint32_t sbase = sb + stage * STAGEB;
#pragma unroll
        for (int it = 0; it < 8; it++) {
            int item = it * 256 + tid;
            int arr = item >> 9, rem = item & 511, r = rem >> 2, kg = rem & 3;
            uint32_t dst = sbase + arr * 10240 + r * ROWB + kg * 16;
            const __nv_bfloat16* src;
            if (arr < 2) {
                int ar = bm + r; if (ar >= M) ar = M - 1;
                src = (arr == 0 ? Ah : Al) + (size_t)ar * 256 + kl + kg * 8;
            } else {
                src = (arr == 2 ? Bhi : Blo) + (size_t)(bn + r) * 512 + k0 + kg * 8;
            }
            CP_ASYNC16(dst, src);
        }
        CP_COMMIT();
    };

    issue_chunk(0, 0);
    for (int c = 0; c < 16; c++) {
        int st = c & 1;
        if (c < 15) {
            issue_chunk(c + 1, st ^ 1);
            asm volatile("cp.async.wait_group 1;" ::: "memory");
        } else {
            asm volatile("cp.async.wait_group 0;" ::: "memory");
        }
        __syncthreads();

        uint32_t Ahb = sb + st * STAGEB;
        uint32_t Alb = Ahb + 10240;
        uint32_t Bhb = Ahb + 20480;
        uint32_t Blb = Ahb + 30720;
        int arow0 = wm * 32 + lr + ((lg & 1) << 3);
        int brow0 = wn * 64 + lr + ((lg >> 1) << 3);
#pragma unroll
        for (int k16 = 0; k16 < 32; k16 += 16) {
            uint32_t akofs = (uint32_t)((k16 + ((lg >> 1) << 3)) * 2);
            uint32_t bkofs = (uint32_t)((k16 + ((lg & 1) << 3)) * 2);
            uint32_t ah[2][4], al[2][4];
            ldsm_x4(ah[0], Ahb + arow0 * ROWB + akofs);
            ldsm_x4(ah[1], Ahb + (arow0 + 16) * ROWB + akofs);
            ldsm_x4(al[0], Alb + arow0 * ROWB + akofs);
            ldsm_x4(al[1], Alb + (arow0 + 16) * ROWB + akofs);
#pragma unroll
            for (int p = 0; p < 4; p++) {
                uint32_t bh[4], bl[4];
                ldsm_x4(bh, Bhb + (brow0 + p * 16) * ROWB + bkofs);
                ldsm_x4(bl, Blb + (brow0 + p * 16) * ROWB + bkofs);
#pragma unroll
                for (int mt = 0; mt < 2; mt++) {
#pragma unroll
                    for (int j = 0; j < 2; j++) {
                        float* a_ = acc[mt][p * 2 + j];
                        mma_bf16(a_, ah[mt], &bh[2 * j]);
                        mma_bf16(a_, ah[mt], &bl[2 * j]);
                        mma_bf16(a_, al[mt], &bh[2 * j]);
                    }
                }
            }
        }
        __syncthreads();
    }

    // --- epilogue: fp32 out (Cf) and/or hi-lo bf16 out (Chi/Clo) ---
#pragma unroll
    for (int mt = 0; mt < 2; mt++) {
        int r0 = bm + wm * 32 + mt * 16 + qr;
#pragma unroll
        for (int nt = 0; nt < 8; nt++) {
            int lc = wn * 64 + nt * 8 + qc;
            int col = bn + lc;
            float b0 = sbias[lc], b1 = sbias[lc + 1];
            float v00 = acc[mt][nt][0] + b0, v01 = acc[mt][nt][1] + b1;
            float v10 = acc[mt][nt][2] + b0, v11 = acc[mt][nt][3] + b1;
            if (Cf) {
                if (r0 < M)
                    *(float2*)&Cf[(size_t)r0 * 256 + col] = make_float2(v00, v01);
                if (r0 + 8 < M)
                    *(float2*)&Cf[(size_t)(r0 + 8) * 256 + col] = make_float2(v10, v11);
            }
            if (Chi) {
                if (r0 < M) {
                    float h0 = bf_hi(v00), h1 = bf_hi(v01);
                    ((uint32_t*)Chi)[((size_t)r0 * 256 + col) >> 1] = pk(h0, h1);
                    ((uint32_t*)Clo)[((size_t)r0 * 256 + col) >> 1] = pk(v00 - h0, v01 - h1);
                }
                if (r0 + 8 < M) {
                    float h0 = bf_hi(v10), h1 = bf_hi(v11);
                    ((uint32_t*)Chi)[((size_t)(r0 + 8) * 256 + col) >> 1] = pk(h0, h1);
                    ((uint32_t*)Clo)[((size_t)(r0 + 8) * 256 + col) >> 1] = pk(v10 - h0, v11 - h1);
                }
            }
        }
    }
}

__global__ void gather_out_kernel(const float* __restrict__ xf,
                                  const int* __restrict__ idxA, int nA,
                                  const int* __restrict__ idxB,
                                  float* __restrict__ out) {
    int r = blockIdx.x;
    int srow = (r < nA) ? idxA[r] : idxB[r - nA];
    ((float4*)(out + (size_t)r * D256))[threadIdx.x] =
        ((const float4*)(xf + (size_t)srow * D256))[threadIdx.x];
}

extern "C" void kernel_launch(void* const* d_in, const int* in_sizes, int n_in,
                              void* d_out, int out_size) {
    const float* emb = (const float*)d_in[0];
    const float* W1l = (const float*)d_in[1];
    const float* b1l = (const float*)d_in[2];
    const float* W1r = (const float*)d_in[3];
    const float* W2l = (const float*)d_in[4];
    const float* b2l = (const float*)d_in[5];
    const float* W2r = (const float*)d_in[6];
    const int* x_idx = (const int*)d_in[7];
    const int* edge  = (const int*)d_in[8];
    const int* drug  = (const int*)d_in[9];
    const int* se    = (const int*)d_in[10];

    int N = in_sizes[7];
    int E = in_sizes[8] / 2;
    const int* src = edge;
    const int* dst = edge + E;
    int nd = in_sizes[9];
    int ns = in_sizes[10];

    float* out   = (float*)d_out;
    float* out_x = out + (size_t)(nd + ns) * D256;

    __nv_bfloat16 *pxhi, *pxlo, *phhi, *phlo, *pmhi, *pmlo, *pbh, *pbl;
    cudaGetSymbolAddress((void**)&pxhi, g_xhi);
    cudaGetSymbolAddress((void**)&pxlo, g_xlo);
    cudaGetSymbolAddress((void**)&phhi, g_hhi);
    cudaGetSymbolAddress((void**)&phlo, g_hlo);
    cudaGetSymbolAddress((void**)&pmhi, g_mhi);
    cudaGetSymbolAddress((void**)&pmlo, g_mlo);
    cudaGetSymbolAddress((void**)&pbh, g_Bhi);
    cudaGetSymbolAddress((void**)&pbl, g_Blo);

    static bool attr_set = false;
    if (!attr_set) {
        cudaFuncSetAttribute(gemm_mma_kernel,
                             cudaFuncAttributeMaxDynamicSharedMemorySize, SM_GEMM);
        attr_set = true;
    }

    int nb = (N + SCAN_BLK - 1) / SCAN_BLK;
    dim3 ggrid(2, (N + 127) / 128);

    // --- CSR build + input gather + weight conversion ---
    zero_cnt_kernel<<<(N + 255) / 256, 256>>>(N);
    gather_x_kernel<<<(N * 32 + 255) / 256, 256>>>(emb, x_idx, N);
    convW_kernel<<<(2 * 256 * 512 + 255) / 256, 256>>>(W1l, W1r, W2l, W2r);
    hist_kernel<<<(E + 255) / 256, 256>>>(dst, E);
    scan_local_kernel<<<nb, SCAN_BLK>>>(N);
    scan_part_kernel<<<1, 1>>>(nb);
    scan_final_kernel<<<nb, SCAN_BLK>>>(N);
    scatter_kernel<<<(E + 255) / 256, 256>>>(src, dst, E);

    // --- layer 1: agg(x hi/lo) -> mean hi/lo ; GEMM -> h hi/lo ONLY ---
    aggregate_kernel<<<(N * 32 + 255) / 256, 256>>>(pxhi, pxlo, N);
    gemm_mma_kernel<<<ggrid, 256, SM_GEMM>>>(pmhi, pmlo, pxhi, pxlo, pbh, pbl,
                                             b1l, nullptr, phhi, phlo, N);

    // --- layer 2: agg(h hi/lo) -> mean hi/lo ; GEMM -> out_x fp32 ---
    aggregate_kernel<<<(N * 32 + 255) / 256, 256>>>(phhi, phlo, N);
    gemm_mma_kernel<<<ggrid, 256, SM_GEMM>>>(pmhi, pmlo, phhi, phlo,
                                             pbh + 256 * 512, pbl + 256 * 512,
                                             b2l, out_x, nullptr, nullptr, N);

    // --- output gathers ---
    gather_out_kernel<<<nd + ns, 64>>>(out_x, drug, nd, se, out);
}

// round 8
// speedup vs baseline: 1.2167x; 1.0055x over previous
#include <cuda_runtime.h>
#include <cuda_bf16.h>
#include <cstdint>

#define D256 256
#define NMAX 100000
#define EMAX 1600000
#define SCAN_BLK 1024

// ---------------- scratch (device globals) ----------------
__device__ __nv_bfloat16 g_xhi[(size_t)NMAX * D256];
__device__ __nv_bfloat16 g_xlo[(size_t)NMAX * D256];
__device__ __nv_bfloat16 g_hhi[(size_t)NMAX * D256];
__device__ __nv_bfloat16 g_hlo[(size_t)NMAX * D256];
__device__ __nv_bfloat16 g_mhi[(size_t)NMAX * D256];
__device__ __nv_bfloat16 g_mlo[(size_t)NMAX * D256];
__device__ int   g_cnt[NMAX + 1];
__device__ int   g_incl[NMAX + 1];
__device__ int   g_rowptr[NMAX + 2];
__device__ int   g_wptr[NMAX + 1];
__device__ int   g_col[EMAX];
__device__ int   g_part[256];
__device__ int   g_poff[256];
// pre-converted weights: [layer][n (256)][k (512)] bf16 hi/lo
__device__ __nv_bfloat16 g_Bhi[2 * 256 * 512];
__device__ __nv_bfloat16 g_Blo[2 * 256 * 512];

// ---------------- helpers ----------------
__device__ __forceinline__ float bf_hi(float v) {
    return __bfloat162float(__float2bfloat16_rn(v));
}
__device__ __forceinline__ uint32_t pk(float a, float b) {
    uint32_t lo = __bfloat16_as_ushort(__float2bfloat16_rn(a));
    uint32_t hi = __bfloat16_as_ushort(__float2bfloat16_rn(b));
    return lo | (hi << 16);
}
__device__ __forceinline__ uint32_t smem_u32(const void* p) {
    uint32_t a;
    asm("{ .reg .u64 t; cvta.to.shared.u64 t, %1; cvt.u32.u64 %0, t; }"
        : "=r"(a) : "l"(p));
    return a;
}
__device__ __forceinline__ void mma_bf16(float* c, const uint32_t* a, const uint32_t* b) {
    asm volatile(
        "mma.sync.aligned.m16n8k16.row.col.f32.bf16.bf16.f32 "
        "{%0,%1,%2,%3}, {%4,%5,%6,%7}, {%8,%9}, {%0,%1,%2,%3};"
        : "+f"(c[0]), "+f"(c[1]), "+f"(c[2]), "+f"(c[3])
        : "r"(a[0]), "r"(a[1]), "r"(a[2]), "r"(a[3]), "r"(b[0]), "r"(b[1]));
}
__device__ __forceinline__ void ldsm_x4(uint32_t* r, uint32_t addr) {
    asm volatile("ldmatrix.sync.aligned.m8n8.x4.shared.b16 {%0,%1,%2,%3}, [%4];"
                 : "=r"(r[0]), "=r"(r[1]), "=r"(r[2]), "=r"(r[3]) : "r"(addr));
}
#define CP_ASYNC16(dst, src) asm volatile( \
    "cp.async.cg.shared.global [%0], [%1], 16;" :: "r"(dst), "l"(src) : "memory")
#define CP_COMMIT() asm volatile("cp.async.commit_group;" ::: "memory")

// accumulate both bf16 halves of packed word w (lo16 = even col, hi16 = odd col)
__device__ __forceinline__ void acc_pair(float& e, float& o, uint32_t w) {
    e += __uint_as_float(w << 16);
    o += __uint_as_float(w & 0xFFFF0000u);
}

// ---------------- small utility kernels ----------------
__global__ void zero_cnt_kernel(int n) {
    int i = blockIdx.x * blockDim.x + threadIdx.x;
    if (i < n) g_cnt[i] = 0;
}
// x = emb[x_idx]; writes ONLY hi/lo bf16 planes
__global__ void gather_x_kernel(const float* __restrict__ emb,
                                const int* __restrict__ idx, int N) {
    int t = blockIdx.x * blockDim.x + threadIdx.x;
    if (t >= N * 32) return;
    int r = t >> 5, c = t & 31;
    const float4* p = (const float4*)emb + (size_t)idx[r] * 64 + c * 2;
    float4 v0 = p[0], v1 = p[1];
    float h0 = bf_hi(v0.x), h1 = bf_hi(v0.y), h2 = bf_hi(v0.z), h3 = bf_hi(v0.w);
    float h4 = bf_hi(v1.x), h5 = bf_hi(v1.y), h6 = bf_hi(v1.z), h7 = bf_hi(v1.w);
    ((uint4*)g_xhi)[(size_t)r * 32 + c] =
        make_uint4(pk(h0, h1), pk(h2, h3), pk(h4, h5), pk(h6, h7));
    ((uint4*)g_xlo)[(size_t)r * 32 + c] =
        make_uint4(pk(v0.x - h0, v0.y - h1), pk(v0.z - h2, v0.w - h3),
                   pk(v1.x - h4, v1.y - h5), pk(v1.z - h6, v1.w - h7));
}
__global__ void hist_kernel(const int* __restrict__ dst, int E) {
    int i = blockIdx.x * blockDim.x + threadIdx.x;
    if (i < E) atomicAdd(&g_cnt[dst[i]], 1);
}
__global__ void scan_local_kernel(int N) {
    __shared__ int s[SCAN_BLK];
    int i = blockIdx.x * SCAN_BLK + threadIdx.x;
    int v = (i < N) ? g_cnt[i] : 0;
    s[threadIdx.x] = v;
    __syncthreads();
    for (int off = 1; off < SCAN_BLK; off <<= 1) {
        int t = (threadIdx.x >= off) ? s[threadIdx.x - off] : 0;
        __syncthreads();
        s[threadIdx.x] += t;
        __syncthreads();
    }
    if (i < N) g_incl[i] = s[threadIdx.x];
    if (threadIdx.x == SCAN_BLK - 1) g_part[blockIdx.x] = s[SCAN_BLK - 1];
}
// parallel exclusive scan of g_part (nb <= 128) — one block of 128 threads
__global__ void scan_part_kernel(int nb) {
    __shared__ int s[128];
    int t = threadIdx.x;
    int v = (t < nb) ? g_part[t] : 0;
    s[t] = v;
    __syncthreads();
    for (int off = 1; off < 128; off <<= 1) {
        int u = (t >= off) ? s[t - off] : 0;
        __syncthreads();
        s[t] += u;
        __syncthreads();
    }
    if (t < nb) g_poff[t] = s[t] - v;   // exclusive
}
__global__ void scan_final_kernel(int N) {
    int i = blockIdx.x * SCAN_BLK + threadIdx.x;
    if (i < N) {
        int v = g_incl[i] + g_poff[blockIdx.x];
        g_rowptr[i + 1] = v;
        g_wptr[i] = v - g_cnt[i];
    }
    if (i == 0) g_rowptr[0] = 0;
}
__global__ void scatter_kernel(const int* __restrict__ src,
                               const int* __restrict__ dst, int E) {
    int i = blockIdx.x * blockDim.x + threadIdx.x;
    if (i < E) {
        int pos = atomicAdd(&g_wptr[dst[i]], 1);
        g_col[pos] = src[i];
    }
}
// mean aggregation: gathers hi/lo bf16 planes, reconstructs (hi+lo), writes mean hi/lo
__global__ void aggregate_kernel(const __nv_bfloat16* __restrict__ xhi,
                                 const __nv_bfloat16* __restrict__ xlo, int N) {
    int warp = (blockIdx.x * blockDim.x + threadIdx.x) >> 5;
    int lane = threadIdx.x & 31;
    if (warp >= N) return;
    int beg = g_rowptr[warp], end = g_rowptr[warp + 1];
    float4 a0 = make_float4(0.f, 0.f, 0.f, 0.f);
    float4 a1 = make_float4(0.f, 0.f, 0.f, 0.f);
    for (int j = beg; j < end; j++) {
        size_t s = (size_t)g_col[j];
        const uint2* rh = (const uint2*)(xhi + s * D256);
        const uint2* rl = (const uint2*)(xlo + s * D256);
        uint2 ha = rh[lane], hb = rh[lane + 32];
        uint2 la = rl[lane], lb = rl[lane + 32];
        acc_pair(a0.x, a0.y, ha.x); acc_pair(a0.z, a0.w, ha.y);
        acc_pair(a1.x, a1.y, hb.x); acc_pair(a1.z, a1.w, hb.y);
        acc_pair(a0.x, a0.y, la.x); acc_pair(a0.z, a0.w, la.y);
        acc_pair(a1.x, a1.y, lb.x); acc_pair(a1.z, a1.w, lb.y);
    }
    int deg = end - beg;
    float sc = 1.0f / (float)(deg > 1 ? deg : 1);
    a0.x *= sc; a0.y *= sc; a0.z *= sc; a0.w *= sc;
    a1.x *= sc; a1.y *= sc; a1.z *= sc; a1.w *= sc;
    float h0 = bf_hi(a0.x), h1 = bf_hi(a0.y), h2 = bf_hi(a0.z), h3 = bf_hi(a0.w);
    float h4 = bf_hi(a1.x), h5 = bf_hi(a1.y), h6 = bf_hi(a1.z), h7 = bf_hi(a1.w);
    uint2* mh = (uint2*)g_mhi + (size_t)warp * 64;
    uint2* ml = (uint2*)g_mlo + (size_t)warp * 64;
    mh[lane]      = make_uint2(pk(h0, h1), pk(h2, h3));
    mh[lane + 32] = make_uint2(pk(h4, h5), pk(h6, h7));
    ml[lane]      = make_uint2(pk(a0.x - h0, a0.y - h1), pk(a0.z - h2, a0.w - h3));
    ml[lane + 32] = make_uint2(pk(a1.x - h4, a1.y - h5), pk(a1.z - h6, a1.w - h7));
}
__global__ void convW_kernel(const float* __restrict__ W1l, const float* __restrict__ W1r,
                             const float* __restrict__ W2l, const float* __restrict__ W2r) {
    int t = blockIdx.x * blockDim.x + threadIdx.x;
    if (t >= 2 * 256 * 512) return;
    int layer = t >> 17;
    int rem = t & 131071;
    int n = rem >> 9;
    int k = rem & 511;
    const float* Wl = layer ? W2l : W1l;
    const float* Wr = layer ? W2r : W1r;
    float v = (k < 256) ? Wl[k * 256 + n] : Wr[(k - 256) * 256 + n];
    __nv_bfloat16 h = __float2bfloat16_rn(v);
    g_Bhi[t] = h;
    g_Blo[t] = __float2bfloat16_rn(v - __bfloat162float(h));
}

// ---------------- pipelined mma.sync GEMM ----------------
// C[M,256] = Am@Wl + Ax@Wr + bias, split-bf16 3-term; A pre-split hi/lo bf16.
// CTA 256 thr, tile 128x128; warp tile 32x64. K: 16 chunks of 32 (8 Am, 8 Ax).
// 2-stage cp.async pipeline; ldmatrix loads; MMA terms interleaved across
// independent accumulators to break RAW chains.
#define ROWB 80
#define STAGEB 40960
#define SM_GEMM (2 * STAGEB + 512)

__global__ void __launch_bounds__(256, 2)
gemm_mma_kernel(const __nv_bfloat16* __restrict__ Amhi, const __nv_bfloat16* __restrict__ Amlo,
                const __nv_bfloat16* __restrict__ Axhi, const __nv_bfloat16* __restrict__ Axlo,
                const __nv_bfloat16* __restrict__ Bhi, const __nv_bfloat16* __restrict__ Blo,
                const float* __restrict__ bias, float* __restrict__ Cf,
                __nv_bfloat16* __restrict__ Chi, __nv_bfloat16* __restrict__ Clo, int M) {
    extern __shared__ char smem[];
    uint32_t sb = smem_u32(smem);
    int tid = threadIdx.x;
    int wid = tid >> 5, lane = tid & 31;
    int wm = wid >> 1, wn = wid & 1;
    int qr = lane >> 2, qc = (lane & 3) * 2;
    int lr = lane & 7, lg = lane >> 3;
    int bm = blockIdx.y * 128;
    int bn = blockIdx.x * 128;

    float* sbias = (float*)(smem + 2 * STAGEB);
    if (tid < 128) sbias[tid] = bias[bn + tid];

    float acc[2][8][4];
#pragma unroll
    for (int i = 0; i < 2; i++)
#pragma unroll
        for (int j = 0; j < 8; j++)
#pragma unroll
            for (int v = 0; v < 4; v++) acc[i][j][v] = 0.f;

    auto issue_chunk = [&](int c, int stage) {
        const __nv_bfloat16* Ah = (c < 8) ? Amhi : Axhi;
        const __nv_bfloat16* Al = (c < 8) ? Amlo : Axlo;
        int kl = (c & 7) * 32;
        int k0 = c * 32;
        uint32_t sbase = sb + stage * STAGEB;
#pragma unroll
        for (int it = 0; it < 8; it++) {
            int item = it * 256 + tid;
            int arr = item >> 9, rem = item & 511, r = rem >> 2, kg = rem & 3;
            uint32_t dst = sbase + arr * 10240 + r * ROWB + kg * 16;
            const __nv_bfloat16* src;
            if (arr < 2) {
                int ar = bm + r; if (ar >= M) ar = M - 1;
                src = (arr == 0 ? Ah : Al) + (size_t)ar * 256 + kl + kg * 8;
            } else {
                src = (arr == 2 ? Bhi : Blo) + (size_t)(bn + r) * 512 + k0 + kg * 8;
            }
            CP_ASYNC16(dst, src);
        }
        CP_COMMIT();
    };

    issue_chunk(0, 0);
    for (int c = 0; c < 16; c++) {
        int st = c & 1;
        if (c < 15) {
            issue_chunk(c + 1, st ^ 1);
            asm volatile("cp.async.wait_group 1;" ::: "memory");
        } else {
            asm volatile("cp.async.wait_group 0;" ::: "memory");
        }
        __syncthreads();

        uint32_t Ahb = sb + st * STAGEB;
        uint32_t Alb = Ahb + 10240;
        uint32_t Bhb = Ahb + 20480;
        uint32_t Blb = Ahb + 30720;
        int arow0 = wm * 32 + lr + ((lg & 1) << 3);
        int brow0 = wn * 64 + lr + ((lg >> 1) << 3);
#pragma unroll
        for (int k16 = 0; k16 < 32; k16 += 16) {
            uint32_t akofs = (uint32_t)((k16 + ((lg >> 1) << 3)) * 2);
            uint32_t bkofs = (uint32_t)((k16 + ((lg & 1) << 3)) * 2);
            uint32_t ah[2][4], al[2][4];
            ldsm_x4(ah[0], Ahb + arow0 * ROWB + akofs);
            ldsm_x4(ah[1], Ahb + (arow0 + 16) * ROWB + akofs);
            ldsm_x4(al[0], Alb + arow0 * ROWB + akofs);
            ldsm_x4(al[1], Alb + (arow0 + 16) * ROWB + akofs);
#pragma unroll
            for (int p = 0; p < 4; p++) {
                uint32_t bh[4], bl[4];
                ldsm_x4(bh, Bhb + (brow0 + p * 16) * ROWB + bkofs);
                ldsm_x4(bl, Blb + (brow0 + p * 16) * ROWB + bkofs);
                // term sweeps: 4 independent accs between any same-acc pair
#pragma unroll
                for (int mt = 0; mt < 2; mt++)
#pragma unroll
                    for (int j = 0; j < 2; j++)
                        mma_bf16(acc[mt][p * 2 + j], ah[mt], &bh[2 * j]);
#pragma unroll
                for (int mt = 0; mt < 2; mt++)
#pragma unroll
                    for (int j = 0; j < 2; j++)
                        mma_bf16(acc[mt][p * 2 + j], ah[mt], &bl[2 * j]);
#pragma unroll
                for (int mt = 0; mt < 2; mt++)
#pragma unroll
                    for (int j = 0; j < 2; j++)
                        mma_bf16(acc[mt][p * 2 + j], al[mt], &bh[2 * j]);
            }
        }
        __syncthreads();
    }

    // --- epilogue: fp32 out (Cf) and/or hi-lo bf16 out (Chi/Clo) ---
#pragma unroll
    for (int mt = 0; mt < 2; mt++) {
        int r0 = bm + wm * 32 + mt * 16 + qr;
#pragma unroll
        for (int nt = 0; nt < 8; nt++) {
            int lc = wn * 64 + nt * 8 + qc;
            int col = bn + lc;
            float b0 = sbias[lc], b1 = sbias[lc + 1];
            float v00 = acc[mt][nt][0] + b0, v01 = acc[mt][nt][1] + b1;
            float v10 = acc[mt][nt][2] + b0, v11 = acc[mt][nt][3] + b1;
            if (Cf) {
                if (r0 < M)
                    *(float2*)&Cf[(size_t)r0 * 256 + col] = make_float2(v00, v01);
                if (r0 + 8 < M)
                    *(float2*)&Cf[(size_t)(r0 + 8) * 256 + col] = make_float2(v10, v11);
            }
            if (Chi) {
                if (r0 < M) {
                    float h0 = bf_hi(v00), h1 = bf_hi(v01);
                    ((uint32_t*)Chi)[((size_t)r0 * 256 + col) >> 1] = pk(h0, h1);
                    ((uint32_t*)Clo)[((size_t)r0 * 256 + col) >> 1] = pk(v00 - h0, v01 - h1);
                }
                if (r0 + 8 < M) {
                    float h0 = bf_hi(v10), h1 = bf_hi(v11);
                    ((uint32_t*)Chi)[((size_t)(r0 + 8) * 256 + col) >> 1] = pk(h0, h1);
                    ((uint32_t*)Clo)[((size_t)(r0 + 8) * 256 + col) >> 1] = pk(v10 - h0, v11 - h1);
                }
            }
        }
    }
}

__global__ void gather_out_kernel(const float* __restrict__ xf,
                                  const int* __restrict__ idxA, int nA,
                                  const int* __restrict__ idxB,
                                  float* __restrict__ out) {
    int r = blockIdx.x;
    int srow = (r < nA) ? idxA[r] : idxB[r - nA];
    ((float4*)(out + (size_t)r * D256))[threadIdx.x] =
        ((const float4*)(xf + (size_t)srow * D256))[threadIdx.x];
}

extern "C" void kernel_launch(void* const* d_in, const int* in_sizes, int n_in,
                              void* d_out, int out_size) {
    const float* emb = (const float*)d_in[0];
    const float* W1l = (const float*)d_in[1];
    const float* b1l = (const float*)d_in[2];
    const float* W1r = (const float*)d_in[3];
    const float* W2l = (const float*)d_in[4];
    const float* b2l = (const float*)d_in[5];
    const float* W2r = (const float*)d_in[6];
    const int* x_idx = (const int*)d_in[7];
    const int* edge  = (const int*)d_in[8];
    const int* drug  = (const int*)d_in[9];
    const int* se    = (const int*)d_in[10];

    int N = in_sizes[7];
    int E = in_sizes[8] / 2;
    const int* src = edge;
    const int* dst = edge + E;
    int nd = in_sizes[9];
    int ns = in_sizes[10];

    float* out   = (float*)d_out;
    float* out_x = out + (size_t)(nd + ns) * D256;

    __nv_bfloat16 *pxhi, *pxlo, *phhi, *phlo, *pmhi, *pmlo, *pbh, *pbl;
    cudaGetSymbolAddress((void**)&pxhi, g_xhi);
    cudaGetSymbolAddress((void**)&pxlo, g_xlo);
    cudaGetSymbolAddress((void**)&phhi, g_hhi);
    cudaGetSymbolAddress((void**)&phlo, g_hlo);
    cudaGetSymbolAddress((void**)&pmhi, g_mhi);
    cudaGetSymbolAddress((void**)&pmlo, g_mlo);
    cudaGetSymbolAddress((void**)&pbh, g_Bhi);
    cudaGetSymbolAddress((void**)&pbl, g_Blo);

    static bool attr_set = false;
    if (!attr_set) {
        cudaFuncSetAttribute(gemm_mma_kernel,
                             cudaFuncAttributeMaxDynamicSharedMemorySize, SM_GEMM);
        attr_set = true;
    }

    int nb = (N + SCAN_BLK - 1) / SCAN_BLK;
    dim3 ggrid(2, (N + 127) / 128);

    // --- CSR build + input gather + weight conversion ---
    zero_cnt_kernel<<<(N + 255) / 256, 256>>>(N);
    gather_x_kernel<<<(N * 32 + 255) / 256, 256>>>(emb, x_idx, N);
    convW_kernel<<<(2 * 256 * 512 + 255) / 256, 256>>>(W1l, W1r, W2l, W2r);
    hist_kernel<<<(E + 255) / 256, 256>>>(dst, E);
    scan_local_kernel<<<nb, SCAN_BLK>>>(N);
    scan_part_kernel<<<1, 128>>>(nb);
    scan_final_kernel<<<nb, SCAN_BLK>>>(N);
    scatter_kernel<<<(E + 255) / 256, 256>>>(src, dst, E);

    // --- layer 1: agg(x hi/lo) -> mean hi/lo ; GEMM -> h hi/lo ONLY ---
    aggregate_kernel<<<(N * 32 + 255) / 256, 256>>>(pxhi, pxlo, N);
    gemm_mma_kernel<<<ggrid, 256, SM_GEMM>>>(pmhi, pmlo, pxhi, pxlo, pbh, pbl,
                                             b1l, nullptr, phhi, phlo, N);

    // --- layer 2: agg(h hi/lo) -> mean hi/lo ; GEMM -> out_x fp32 ---
    aggregate_kernel<<<(N * 32 + 255) / 256, 256>>>(phhi, phlo, N);
    gemm_mma_kernel<<<ggrid, 256, SM_GEMM>>>(pmhi, pmlo, phhi, phlo,
                                             pbh + 256 * 512, pbl + 256 * 512,
                                             b2l, out_x, nullptr, nullptr, N);

    // --- output gathers ---
    gather_out_kernel<<<nd + ns, 64>>>(out_x, drug, nd, se, out);
}

// round 9
// speedup vs baseline: 1.2189x; 1.0018x over previous
#include <cuda_runtime.h>
#include <cuda_bf16.h>
#include <cstdint>

#define D256 256
#define NMAX 100000
#define EMAX 1600000
#define SCAN_BLK 1024

// ---------------- scratch (device globals) ----------------
__device__ __nv_bfloat16 g_xhi[(size_t)NMAX * D256];
__device__ __nv_bfloat16 g_xlo[(size_t)NMAX * D256];
__device__ __nv_bfloat16 g_hhi[(size_t)NMAX * D256];
__device__ __nv_bfloat16 g_hlo[(size_t)NMAX * D256];
__device__ __nv_bfloat16 g_mhi[(size_t)NMAX * D256];
__device__ __nv_bfloat16 g_mlo[(size_t)NMAX * D256];
__device__ int   g_cnt[NMAX + 1];
__device__ int   g_incl[NMAX + 1];
__device__ int   g_rowptr[NMAX + 2];
__device__ int   g_wptr[NMAX + 1];
__device__ int   g_col[EMAX];
__device__ int   g_part[256];
__device__ int   g_poff[256];
// pre-converted weights: [layer][n (256)][k (512)] bf16 hi/lo
__device__ __nv_bfloat16 g_Bhi[2 * 256 * 512];
__device__ __nv_bfloat16 g_Blo[2 * 256 * 512];

// ---------------- helpers ----------------
__device__ __forceinline__ float bf_hi(float v) {
    return __bfloat162float(__float2bfloat16_rn(v));
}
__device__ __forceinline__ uint32_t pk(float a, float b) {
    uint32_t lo = __bfloat16_as_ushort(__float2bfloat16_rn(a));
    uint32_t hi = __bfloat16_as_ushort(__float2bfloat16_rn(b));
    return lo | (hi << 16);
}
__device__ __forceinline__ uint32_t smem_u32(const void* p) {
    uint32_t a;
    asm("{ .reg .u64 t; cvta.to.shared.u64 t, %1; cvt.u32.u64 %0, t; }"
        : "=r"(a) : "l"(p));
    return a;
}
__device__ __forceinline__ void mma_bf16(float* c, const uint32_t* a, const uint32_t* b) {
    asm volatile(
        "mma.sync.aligned.m16n8k16.row.col.f32.bf16.bf16.f32 "
        "{%0,%1,%2,%3}, {%4,%5,%6,%7}, {%8,%9}, {%0,%1,%2,%3};"
        : "+f"(c[0]), "+f"(c[1]), "+f"(c[2]), "+f"(c[3])
        : "r"(a[0]), "r"(a[1]), "r"(a[2]), "r"(a[3]), "r"(b[0]), "r"(b[1]));
}
__device__ __forceinline__ void ldsm_x4(uint32_t* r, uint32_t addr) {
    asm volatile("ldmatrix.sync.aligned.m8n8.x4.shared.b16 {%0,%1,%2,%3}, [%4];"
                 : "=r"(r[0]), "=r"(r[1]), "=r"(r[2]), "=r"(r[3]) : "r"(addr));
}
#define CP_ASYNC16(dst, src) asm volatile( \
    "cp.async.cg.shared.global [%0], [%1], 16;" :: "r"(dst), "l"(src) : "memory")
#define CP_COMMIT() asm volatile("cp.async.commit_group;" ::: "memory")

// accumulate both bf16 halves of packed word w (lo16 = even col, hi16 = odd col)
__device__ __forceinline__ void acc_pair(float& e, float& o, uint32_t w) {
    e += __uint_as_float(w << 16);
    o += __uint_as_float(w & 0xFFFF0000u);
}

// ---------------- small utility kernels ----------------
__global__ void zero_cnt_kernel(int n) {
    int i = blockIdx.x * blockDim.x + threadIdx.x;
    if (i < n) g_cnt[i] = 0;
}
// x = emb[x_idx]; writes ONLY hi/lo bf16 planes
__global__ void gather_x_kernel(const float* __restrict__ emb,
                                const int* __restrict__ idx, int N) {
    int t = blockIdx.x * blockDim.x + threadIdx.x;
    if (t >= N * 32) return;
    int r = t >> 5, c = t & 31;
    const float4* p = (const float4*)emb + (size_t)idx[r] * 64 + c * 2;
    float4 v0 = p[0], v1 = p[1];
    float h0 = bf_hi(v0.x), h1 = bf_hi(v0.y), h2 = bf_hi(v0.z), h3 = bf_hi(v0.w);
    float h4 = bf_hi(v1.x), h5 = bf_hi(v1.y), h6 = bf_hi(v1.z), h7 = bf_hi(v1.w);
    ((uint4*)g_xhi)[(size_t)r * 32 + c] =
        make_uint4(pk(h0, h1), pk(h2, h3), pk(h4, h5), pk(h6, h7));
    ((uint4*)g_xlo)[(size_t)r * 32 + c] =
        make_uint4(pk(v0.x - h0, v0.y - h1), pk(v0.z - h2, v0.w - h3),
                   pk(v1.x - h4, v1.y - h5), pk(v1.z - h6, v1.w - h7));
}
__global__ void hist_kernel(const int* __restrict__ dst, int E) {
    int i = blockIdx.x * blockDim.x + threadIdx.x;
    if (i < E) atomicAdd(&g_cnt[dst[i]], 1);
}
__global__ void scan_local_kernel(int N) {
    __shared__ int s[SCAN_BLK];
    int i = blockIdx.x * SCAN_BLK + threadIdx.x;
    int v = (i < N) ? g_cnt[i] : 0;
    s[threadIdx.x] = v;
    __syncthreads();
    for (int off = 1; off < SCAN_BLK; off <<= 1) {
        int t = (threadIdx.x >= off) ? s[threadIdx.x - off] : 0;
        __syncthreads();
        s[threadIdx.x] += t;
        __syncthreads();
    }
    if (i < N) g_incl[i] = s[threadIdx.x];
    if (threadIdx.x == SCAN_BLK - 1) g_part[blockIdx.x] = s[SCAN_BLK - 1];
}
// parallel exclusive scan of g_part (nb <= 128) — one block of 128 threads
__global__ void scan_part_kernel(int nb) {
    __shared__ int s[128];
    int t = threadIdx.x;
    int v = (t < nb) ? g_part[t] : 0;
    s[t] = v;
    __syncthreads();
    for (int off = 1; off < 128; off <<= 1) {
        int u = (t >= off) ? s[t - off] : 0;
        __syncthreads();
        s[t] += u;
        __syncthreads();
    }
    if (t < nb) g_poff[t] = s[t] - v;   // exclusive
}
__global__ void scan_final_kernel(int N) {
    int i = blockIdx.x * SCAN_BLK + threadIdx.x;
    if (i < N) {
        int v = g_incl[i] + g_poff[blockIdx.x];
        g_rowptr[i + 1] = v;
        g_wptr[i] = v - g_cnt[i];
    }
    if (i == 0) g_rowptr[0] = 0;
}
__global__ void scatter_kernel(const int* __restrict__ src,
                               const int* __restrict__ dst, int E) {
    int i = blockIdx.x * blockDim.x + threadIdx.x;
    if (i < E) {
        int pos = atomicAdd(&g_wptr[dst[i]], 1);
        g_col[pos] = src[i];
    }
}
// mean aggregation: gathers hi/lo bf16 planes; 2-edge unroll for MLP
__global__ void aggregate_kernel(const __nv_bfloat16* __restrict__ xhi,
                                 const __nv_bfloat16* __restrict__ xlo, int N) {
    int warp = (blockIdx.x * blockDim.x + threadIdx.x) >> 5;
    int lane = threadIdx.x & 31;
    if (warp >= N) return;
    int beg = g_rowptr[warp], end = g_rowptr[warp + 1];
    float4 a0 = make_float4(0.f, 0.f, 0.f, 0.f);
    float4 a1 = make_float4(0.f, 0.f, 0.f, 0.f);
    int j = beg;
    for (; j + 1 < end; j += 2) {
        size_t s0 = (size_t)g_col[j];
        size_t s1 = (size_t)g_col[j + 1];
        const uint2* rh0 = (const uint2*)(xhi + s0 * D256);
        const uint2* rl0 = (const uint2*)(xlo + s0 * D256);
        const uint2* rh1 = (const uint2*)(xhi + s1 * D256);
        const uint2* rl1 = (const uint2*)(xlo + s1 * D256);
        uint2 ha0 = rh0[lane], hb0 = rh0[lane + 32];
        uint2 la0 = rl0[lane], lb0 = rl0[lane + 32];
        uint2 ha1 = rh1[lane], hb1 = rh1[lane + 32];
        uint2 la1 = rl1[lane], lb1 = rl1[lane + 32];
        acc_pair(a0.x, a0.y, ha0.x); acc_pair(a0.z, a0.w, ha0.y);
        acc_pair(a1.x, a1.y, hb0.x); acc_pair(a1.z, a1.w, hb0.y);
        acc_pair(a0.x, a0.y, la0.x); acc_pair(a0.z, a0.w, la0.y);
        acc_pair(a1.x, a1.y, lb0.x); acc_pair(a1.z, a1.w, lb0.y);
        acc_pair(a0.x, a0.y, ha1.x); acc_pair(a0.z, a0.w, ha1.y);
        acc_pair(a1.x, a1.y, hb1.x); acc_pair(a1.z, a1.w, hb1.y);
        acc_pair(a0.x, a0.y, la1.x); acc_pair(a0.z, a0.w, la1.y);
        acc_pair(a1.x, a1.y, lb1.x); acc_pair(a1.z, a1.w, lb1.y);
    }
    if (j < end) {
        size_t s = (size_t)g_col[j];
        const uint2* rh = (const uint2*)(xhi + s * D256);
        const uint2* rl = (const uint2*)(xlo + s * D256);
        uint2 ha = rh[lane], hb = rh[lane + 32];
        uint2 la = rl[lane], lb = rl[lane + 32];
        acc_pair(a0.x, a0.y, ha.x); acc_pair(a0.z, a0.w, ha.y);
        acc_pair(a1.x, a1.y, hb.x); acc_pair(a1.z, a1.w, hb.y);
        acc_pair(a0.x, a0.y, la.x); acc_pair(a0.z, a0.w, la.y);
        acc_pair(a1.x, a1.y, lb.x); acc_pair(a1.z, a1.w, lb.y);
    }
    int deg = end - beg;
    float sc = 1.0f / (float)(deg > 1 ? deg : 1);
    a0.x *= sc; a0.y *= sc; a0.z *= sc; a0.w *= sc;
    a1.x *= sc; a1.y *= sc; a1.z *= sc; a1.w *= sc;
    float h0 = bf_hi(a0.x), h1 = bf_hi(a0.y), h2 = bf_hi(a0.z), h3 = bf_hi(a0.w);
    float h4 = bf_hi(a1.x), h5 = bf_hi(a1.y), h6 = bf_hi(a1.z), h7 = bf_hi(a1.w);
    uint2* mh = (uint2*)g_mhi + (size_t)warp * 64;
    uint2* ml = (uint2*)g_mlo + (size_t)warp * 64;
    mh[lane]      = make_uint2(pk(h0, h1), pk(h2, h3));
    mh[lane + 32] = make_uint2(pk(h4, h5), pk(h6, h7));
    ml[lane]      = make_uint2(pk(a0.x - h0, a0.y - h1), pk(a0.z - h2, a0.w - h3));
    ml[lane + 32] = make_uint2(pk(a1.x - h4, a1.y - h5), pk(a1.z - h6, a1.w - h7));
}
__global__ void convW_kernel(const float* __restrict__ W1l, const float* __restrict__ W1r,
                             const float* __restrict__ W2l, const float* __restrict__ W2r) {
    int t = blockIdx.x * blockDim.x + threadIdx.x;
    if (t >= 2 * 256 * 512) return;
    int layer = t >> 17;
    int rem = t & 131071;
    int n = rem >> 9;
    int k = rem & 511;
    const float* Wl = layer ? W2l : W1l;
    const float* Wr = layer ? W2r : W1r;
    float v = (k < 256) ? Wl[k * 256 + n] : Wr[(k - 256) * 256 + n];
    __nv_bfloat16 h = __float2bfloat16_rn(v);
    g_Bhi[t] = h;
    g_Blo[t] = __float2bfloat16_rn(v - __bfloat162float(h));
}

// ---------------- persistent pipelined mma.sync GEMM ----------------
// C[M,256] = Am@Wl + Ax@Wr + bias, split-bf16 3-term; A pre-split hi/lo bf16.
// CTA 256 thr, tile 128x128; warp tile 32x64. K: 16 chunks of 32 (8 Am, 8 Ax).
// Persistent: grid = 2*numSMs; each CTA loops over tiles; (tile,chunk) space
// flattened so the 2-stage cp.async pipeline runs across tile boundaries.
#define ROWB 80
#define STAGEB 40960
#define SM_GEMM (2 * STAGEB)

__global__ void __launch_bounds__(256, 2)
gemm_mma_kernel(const __nv_bfloat16* __restrict__ Amhi, const __nv_bfloat16* __restrict__ Amlo,
                const __nv_bfloat16* __restrict__ Axhi, const __nv_bfloat16* __restrict__ Axlo,
                const __nv_bfloat16* __restrict__ Bhi, const __nv_bfloat16* __restrict__ Blo,
                const float* __restrict__ bias, float* __restrict__ Cf,
                __nv_bfloat16* __restrict__ Chi, __nv_bfloat16* __restrict__ Clo,
                int M, int ntiles) {
    extern __shared__ char smem[];
    uint32_t sb = smem_u32(smem);
    int tid = threadIdx.x;
    int wid = tid >> 5, lane = tid & 31;
    int wm = wid >> 1, wn = wid & 1;
    int qr = lane >> 2, qc = (lane & 3) * 2;
    int lr = lane & 7, lg = lane >> 3;

    int stride = gridDim.x;
    int count = (ntiles - (int)blockIdx.x + stride - 1) / stride;
    if (count <= 0) return;
    int total_i = count * 16;

    float acc[2][8][4];
#pragma unroll
    for (int i = 0; i < 2; i++)
#pragma unroll
        for (int j = 0; j < 8; j++)
#pragma unroll
            for (int v = 0; v < 4; v++) acc[i][j][v] = 0.f;

    // issue chunk for flattened iteration gi into stage
    auto issue_i = [&](int gi, int stage) {
        int t = (int)blockIdx.x + (gi >> 4) * stride;
        int c = gi & 15;
        int bm = (t >> 1) * 128;
        int bn = (t & 1) * 128;
        const __nv_bfloat16* Ah = (c < 8) ? Amhi : Axhi;
        const __nv_bfloat16* Al = (c < 8) ? Amlo : Axlo;
        int kl = (c & 7) * 32;
        int k0 = c * 32;
        uint32_t sbase = sb + stage * STAGEB;
#pragma unroll
        for (int it = 0; it < 8; it++) {
            int item = it * 256 + tid;
            int arr = item >> 9, rem = item & 511, r = rem >> 2, kg = rem & 3;
            uint32_t dst = sbase + arr * 10240 + r * ROWB + kg * 16;
            const __nv_bfloat16* src;
            if (arr < 2) {
                int ar = bm + r; if (ar >= M) ar = M - 1;
                src = (arr == 0 ? Ah : Al) + (size_t)ar * 256 + kl + kg * 8;
            } else {
                src = (arr == 2 ? Bhi : Blo) + (size_t)(bn + r) * 512 + k0 + kg * 8;
            }
            CP_ASYNC16(dst, src);
        }
        CP_COMMIT();
    };

    issue_i(0, 0);
    for (int gi = 0; gi < total_i; gi++) {
        int st = gi & 1;
        if (gi + 1 < total_i) {
            issue_i(gi + 1, st ^ 1);
            asm volatile("cp.async.wait_group 1;" ::: "memory");
        } else {
            asm volatile("cp.async.wait_group 0;" ::: "memory");
        }
        __syncthreads();

        uint32_t Ahb = sb + st * STAGEB;
        uint32_t Alb = Ahb + 10240;
        uint32_t Bhb = Ahb + 20480;
        uint32_t Blb = Ahb + 30720;
        int arow0 = wm * 32 + lr + ((lg & 1) << 3);
        int brow0 = wn * 64 + lr + ((lg >> 1) << 3);
#pragma unroll
        for (int k16 = 0; k16 < 32; k16 += 16) {
            uint32_t akofs = (uint32_t)((k16 + ((lg >> 1) << 3)) * 2);
            uint32_t bkofs = (uint32_t)((k16 + ((lg & 1) << 3)) * 2);
            uint32_t ah[2][4], al[2][4];
            ldsm_x4(ah[0], Ahb + arow0 * ROWB + akofs);
            ldsm_x4(ah[1], Ahb + (arow0 + 16) * ROWB + akofs);
            ldsm_x4(al[0], Alb + arow0 * ROWB + akofs);
            ldsm_x4(al[1], Alb + (arow0 + 16) * ROWB + akofs);
#pragma unroll
            for (int p = 0; p < 4; p++) {
                uint32_t bh[4], bl[4];
                ldsm_x4(bh, Bhb + (brow0 + p * 16) * ROWB + bkofs);
                ldsm_x4(bl, Blb + (brow0 + p * 16) * ROWB + bkofs);
#pragma unroll
                for (int mt = 0; mt < 2; mt++)
#pragma unroll
                    for (int j = 0; j < 2; j++)
                        mma_bf16(acc[mt][p * 2 + j], ah[mt], &bh[2 * j]);
#pragma unroll
                for (int mt = 0; mt < 2; mt++)
#pragma unroll
                    for (int j = 0; j < 2; j++)
                        mma_bf16(acc[mt][p * 2 + j], ah[mt], &bl[2 * j]);
#pragma unroll
                for (int mt = 0; mt < 2; mt++)
#pragma unroll
                    for (int j = 0; j < 2; j++)
                        mma_bf16(acc[mt][p * 2 + j], al[mt], &bh[2 * j]);
            }
        }
        __syncthreads();

        if ((gi & 15) == 15) {
            // epilogue for this tile (overlaps next tile's chunk-0 DMA)
            int t = (int)blockIdx.x + (gi >> 4) * stride;
            int bm = (t >> 1) * 128;
            int bn = (t & 1) * 128;
#pragma unroll
            for (int mt = 0; mt < 2; mt++) {
                int r0 = bm + wm * 32 + mt * 16 + qr;
#pragma unroll
                for (int nt = 0; nt < 8; nt++) {
                    int col = bn + wn * 64 + nt * 8 + qc;
                    float2 bv = __ldg((const float2*)&bias[col]);
                    float v00 = acc[mt][nt][0] + bv.x, v01 = acc[mt][nt][1] + bv.y;
                    float v10 = acc[mt][nt][2] + bv.x, v11 = acc[mt][nt][3] + bv.y;
                    if (Cf) {
                        if (r0 < M)
                            *(float2*)&Cf[(size_t)r0 * 256 + col] = make_float2(v00, v01);
                        if (r0 + 8 < M)
                            *(float2*)&Cf[(size_t)(r0 + 8) * 256 + col] = make_float2(v10, v11);
                    }
                    if (Chi) {
                        if (r0 < M) {
                            float h0 = bf_hi(v00), h1 = bf_hi(v01);
                            ((uint32_t*)Chi)[((size_t)r0 * 256 + col) >> 1] = pk(h0, h1);
                            ((uint32_t*)Clo)[((size_t)r0 * 256 + col) >> 1] = pk(v00 - h0, v01 - h1);
                        }
                        if (r0 + 8 < M) {
                            float h0 = bf_hi(v10), h1 = bf_hi(v11);
                            ((uint32_t*)Chi)[((size_t)(r0 + 8) * 256 + col) >> 1] = pk(h0, h1);
                            ((uint32_t*)Clo)[((size_t)(r0 + 8) * 256 + col) >> 1] = pk(v10 - h0, v11 - h1);
                        }
                    }
                }
            }
#pragma unroll
            for (int i = 0; i < 2; i++)
#pragma unroll
                for (int j = 0; j < 8; j++)
#pragma unroll
                    for (int v = 0; v < 4; v++) acc[i][j][v] = 0.f;
        }
    }
}

__global__ void gather_out_kernel(const float* __restrict__ xf,
                                  const int* __restrict__ idxA, int nA,
                                  const int* __restrict__ idxB,
                                  float* __restrict__ out) {
    int r = blockIdx.x;
    int srow = (r < nA) ? idxA[r] : idxB[r - nA];
    ((float4*)(out + (size_t)r * D256))[threadIdx.x] =
        ((const float4*)(xf + (size_t)srow * D256))[threadIdx.x];
}

extern "C" void kernel_launch(void* const* d_in, const int* in_sizes, int n_in,
                              void* d_out, int out_size) {
    const float* emb = (const float*)d_in[0];
    const float* W1l = (const float*)d_in[1];
    const float* b1l = (const float*)d_in[2];
    const float* W1r = (const float*)d_in[3];
    const float* W2l = (const float*)d_in[4];
    const float* b2l = (const float*)d_in[5];
    const float* W2r = (const float*)d_in[6];
    const int* x_idx = (const int*)d_in[7];
    const int* edge  = (const int*)d_in[8];
    const int* drug  = (const int*)d_in[9];
    const int* se    = (const int*)d_in[10];

    int N = in_sizes[7];
    int E = in_sizes[8] / 2;
    const int* src = edge;
    const int* dst = edge + E;
    int nd = in_sizes[9];
    int ns = in_sizes[10];

    float* out   = (float*)d_out;
    float* out_x = out + (size_t)(nd + ns) * D256;

    __nv_bfloat16 *pxhi, *pxlo, *phhi, *phlo, *pmhi, *pmlo, *pbh, *pbl;
    cudaGetSymbolAddress((void**)&pxhi, g_xhi);
    cudaGetSymbolAddress((void**)&pxlo, g_xlo);
    cudaGetSymbolAddress((void**)&phhi, g_hhi);
    cudaGetSymbolAddress((void**)&phlo, g_hlo);
    cudaGetSymbolAddress((void**)&pmhi, g_mhi);
    cudaGetSymbolAddress((void**)&pmlo, g_mlo);
    cudaGetSymbolAddress((void**)&pbh, g_Bhi);
    cudaGetSymbolAddress((void**)&pbl, g_Blo);

    static int nsm = 0;
    if (!nsm) {
        cudaDeviceGetAttribute(&nsm, cudaDevAttrMultiProcessorCount, 0);
        if (nsm <= 0) nsm = 148;
        cudaFuncSetAttribute(gemm_mma_kernel,
                             cudaFuncAttributeMaxDynamicSharedMemorySize, SM_GEMM);
    }

    int nb = (N + SCAN_BLK - 1) / SCAN_BLK;
    int ntiles = 2 * ((N + 127) / 128);
    int pgrid = 2 * nsm;
    if (pgrid > ntiles) pgrid = ntiles;

    // --- CSR build + input gather + weight conversion ---
    zero_cnt_kernel<<<(N + 255) / 256, 256>>>(N);
    gather_x_kernel<<<(N * 32 + 255) / 256, 256>>>(emb, x_idx, N);
    convW_kernel<<<(2 * 256 * 512 + 255) / 256, 256>>>(W1l, W1r, W2l, W2r);
    hist_kernel<<<(E + 255) / 256, 256>>>(dst, E);
    scan_local_kernel<<<nb, SCAN_BLK>>>(N);
    scan_part_kernel<<<1, 128>>>(nb);
    scan_final_kernel<<<nb, SCAN_BLK>>>(N);
    scatter_kernel<<<(E + 255) / 256, 256>>>(src, dst, E);

    // --- layer 1: agg(x hi/lo) -> mean hi/lo ; GEMM -> h hi/lo ONLY ---
    aggregate_kernel<<<(N * 32 + 255) / 256, 256>>>(pxhi, pxlo, N);
    gemm_mma_kernel<<<pgrid, 256, SM_GEMM>>>(pmhi, pmlo, pxhi, pxlo, pbh, pbl,
                                             b1l, nullptr, phhi, phlo, N, ntiles);

    // --- layer 2: agg(h hi/lo) -> mean hi/lo ; GEMM -> out_x fp32 ---
    aggregate_kernel<<<(N * 32 + 255) / 256, 256>>>(phhi, phlo, N);
    gemm_mma_kernel<<<pgrid, 256, SM_GEMM>>>(pmhi, pmlo, phhi, phlo,
                                             pbh + 256 * 512, pbl + 256 * 512,
                                             b2l, out_x, nullptr, nullptr, N, ntiles);

    // --- output gathers ---
    gather_out_kernel<<<nd + ns, 64>>>(out_x, drug, nd, se, out);
}

// round 10
// speedup vs baseline: 1.3672x; 1.1216x over previous
#include <cuda_runtime.h>
#include <cuda_bf16.h>
#include <cuda_fp16.h>
#include <cstdint>

#define D256 256
#define NMAX 100000
#define EMAX 1600000
#define SCAN_BLK 1024

// ---------------- scratch (device globals) ----------------
__device__ __nv_bfloat16 g_xhi[(size_t)NMAX * D256];
__device__ __nv_bfloat16 g_xlo[(size_t)NMAX * D256];
__device__ __half        g_xf16[(size_t)NMAX * D256];   // agg-only plane
__device__ __nv_bfloat16 g_hhi[(size_t)NMAX * D256];
__device__ __nv_bfloat16 g_hlo[(size_t)NMAX * D256];
__device__ __half        g_hf16[(size_t)NMAX * D256];   // agg-only plane
__device__ __nv_bfloat16 g_mhi[(size_t)NMAX * D256];
__device__ __nv_bfloat16 g_mlo[(size_t)NMAX * D256];
__device__ int   g_cnt[NMAX + 1];
__device__ int   g_incl[NMAX + 1];
__device__ int   g_rowptr[NMAX + 2];
__device__ int   g_wptr[NMAX + 1];
__device__ int   g_col[EMAX];
__device__ int   g_part[256];
__device__ int   g_poff[256];
// pre-converted weights: [layer][n (256)][k (512)] bf16 hi/lo
__device__ __nv_bfloat16 g_Bhi[2 * 256 * 512];
__device__ __nv_bfloat16 g_Blo[2 * 256 * 512];

// ---------------- helpers ----------------
__device__ __forceinline__ float bf_hi(float v) {
    return __bfloat162float(__float2bfloat16_rn(v));
}
__device__ __forceinline__ uint32_t pk(float a, float b) {
    uint32_t lo = __bfloat16_as_ushort(__float2bfloat16_rn(a));
    uint32_t hi = __bfloat16_as_ushort(__float2bfloat16_rn(b));
    return lo | (hi << 16);
}
__device__ __forceinline__ uint32_t pkh(float a, float b) {
    __half2 h = __floats2half2_rn(a, b);
    return *(uint32_t*)&h;
}
__device__ __forceinline__ uint32_t smem_u32(const void* p) {
    uint32_t a;
    asm("{ .reg .u64 t; cvta.to.shared.u64 t, %1; cvt.u32.u64 %0, t; }"
        : "=r"(a) : "l"(p));
    return a;
}
__device__ __forceinline__ void mma_bf16(float* c, const uint32_t* a, const uint32_t* b) {
    asm volatile(
        "mma.sync.aligned.m16n8k16.row.col.f32.bf16.bf16.f32 "
        "{%0,%1,%2,%3}, {%4,%5,%6,%7}, {%8,%9}, {%0,%1,%2,%3};"
        : "+f"(c[0]), "+f"(c[1]), "+f"(c[2]), "+f"(c[3])
        : "r"(a[0]), "r"(a[1]), "r"(a[2]), "r"(a[3]), "r"(b[0]), "r"(b[1]));
}
__device__ __forceinline__ void ldsm_x4(uint32_t* r, uint32_t addr) {
    asm volatile("ldmatrix.sync.aligned.m8n8.x4.shared.b16 {%0,%1,%2,%3}, [%4];"
                 : "=r"(r[0]), "=r"(r[1]), "=r"(r[2]), "=r"(r[3]) : "r"(addr));
}
#define CP_ASYNC16(dst, src) asm volatile( \
    "cp.async.cg.shared.global [%0], [%1], 16;" :: "r"(dst), "l"(src) : "memory")
#define CP_COMMIT() asm volatile("cp.async.commit_group;" ::: "memory")

// accumulate a packed half2 word into two fp32 accs
__device__ __forceinline__ void acc_h2(float& e, float& o, uint32_t w) {
    float2 f = __half22float2(*(const __half2*)&w);
    e += f.x; o += f.y;
}

// ---------------- small utility kernels ----------------
__global__ void zero_cnt_kernel(int n) {
    int i = blockIdx.x * blockDim.x + threadIdx.x;
    if (i < n) g_cnt[i] = 0;
}
// x = emb[x_idx]; writes hi/lo bf16 planes (GEMM) + fp16 plane (aggregation)
__global__ void gather_x_kernel(const float* __restrict__ emb,
                                const int* __restrict__ idx, int N) {
    int t = blockIdx.x * blockDim.x + threadIdx.x;
    if (t >= N * 32) return;
    int r = t >> 5, c = t & 31;
    const float4* p = (const float4*)emb + (size_t)idx[r] * 64 + c * 2;
    float4 v0 = p[0], v1 = p[1];
    float h0 = bf_hi(v0.x), h1 = bf_hi(v0.y), h2 = bf_hi(v0.z), h3 = bf_hi(v0.w);
    float h4 = bf_hi(v1.x), h5 = bf_hi(v1.y), h6 = bf_hi(v1.z), h7 = bf_hi(v1.w);
    ((uint4*)g_xhi)[(size_t)r * 32 + c] =
        make_uint4(pk(h0, h1), pk(h2, h3), pk(h4, h5), pk(h6, h7));
    ((uint4*)g_xlo)[(size_t)r * 32 + c] =
        make_uint4(pk(v0.x - h0, v0.y - h1), pk(v0.z - h2, v0.w - h3),
                   pk(v1.x - h4, v1.y - h5), pk(v1.z - h6, v1.w - h7));
    ((uint4*)g_xf16)[(size_t)r * 32 + c] =
        make_uint4(pkh(v0.x, v0.y), pkh(v0.z, v0.w), pkh(v1.x, v1.y), pkh(v1.z, v1.w));
}
__global__ void hist_kernel(const int* __restrict__ dst, int E) {
    int i = blockIdx.x * blockDim.x + threadIdx.x;
    if (i < E) atomicAdd(&g_cnt[dst[i]], 1);
}
__global__ void scan_local_kernel(int N) {
    __shared__ int s[SCAN_BLK];
    int i = blockIdx.x * SCAN_BLK + threadIdx.x;
    int v = (i < N) ? g_cnt[i] : 0;
    s[threadIdx.x] = v;
    __syncthreads();
    for (int off = 1; off < SCAN_BLK; off <<= 1) {
        int t = (threadIdx.x >= off) ? s[threadIdx.x - off] : 0;
        __syncthreads();
        s[threadIdx.x] += t;
        __syncthreads();
    }
    if (i < N) g_incl[i] = s[threadIdx.x];
    if (threadIdx.x == SCAN_BLK - 1) g_part[blockIdx.x] = s[SCAN_BLK - 1];
}
__global__ void scan_part_kernel(int nb) {
    __shared__ int s[128];
    int t = threadIdx.x;
    int v = (t < nb) ? g_part[t] : 0;
    s[t] = v;
    __syncthreads();
    for (int off = 1; off < 128; off <<= 1) {
        int u = (t >= off) ? s[t - off] : 0;
        __syncthreads();
        s[t] += u;
        __syncthreads();
    }
    if (t < nb) g_poff[t] = s[t] - v;   // exclusive
}
__global__ void scan_final_kernel(int N) {
    int i = blockIdx.x * SCAN_BLK + threadIdx.x;
    if (i < N) {
        int v = g_incl[i] + g_poff[blockIdx.x];
        g_rowptr[i + 1] = v;
        g_wptr[i] = v - g_cnt[i];
    }
    if (i == 0) g_rowptr[0] = 0;
}
__global__ void scatter_kernel(const int* __restrict__ src,
                               const int* __restrict__ dst, int E) {
    int i = blockIdx.x * blockDim.x + threadIdx.x;
    if (i < E) {
        int pos = atomicAdd(&g_wptr[dst[i]], 1);
        g_col[pos] = src[i];
    }
}
// mean aggregation: gathers single fp16 plane (half the bytes), fp32 accumulate,
// writes mean as bf16 hi/lo for the GEMM. 2-edge unroll.
__global__ void aggregate_kernel(const __half* __restrict__ xf, int N) {
    int warp = (blockIdx.x * blockDim.x + threadIdx.x) >> 5;
    int lane = threadIdx.x & 31;
    if (warp >= N) return;
    int beg = g_rowptr[warp], end = g_rowptr[warp + 1];
    float4 a0 = make_float4(0.f, 0.f, 0.f, 0.f);
    float4 a1 = make_float4(0.f, 0.f, 0.f, 0.f);
    int j = beg;
    for (; j + 1 < end; j += 2) {
        const uint2* r0 = (const uint2*)(xf + (size_t)g_col[j] * D256);
        const uint2* r1 = (const uint2*)(xf + (size_t)g_col[j + 1] * D256);
        uint2 va0 = r0[lane], vb0 = r0[lane + 32];
        uint2 va1 = r1[lane], vb1 = r1[lane + 32];
        acc_h2(a0.x, a0.y, va0.x); acc_h2(a0.z, a0.w, va0.y);
        acc_h2(a1.x, a1.y, vb0.x); acc_h2(a1.z, a1.w, vb0.y);
        acc_h2(a0.x, a0.y, va1.x); acc_h2(a0.z, a0.w, va1.y);
        acc_h2(a1.x, a1.y, vb1.x); acc_h2(a1.z, a1.w, vb1.y);
    }
    if (j < end) {
        const uint2* r0 = (const uint2*)(xf + (size_t)g_col[j] * D256);
        uint2 va = r0[lane], vb = r0[lane + 32];
        acc_h2(a0.x, a0.y, va.x); acc_h2(a0.z, a0.w, va.y);
        acc_h2(a1.x, a1.y, vb.x); acc_h2(a1.z, a1.w, vb.y);
    }
    int deg = end - beg;
    float sc = 1.0f / (float)(deg > 1 ? deg : 1);
    a0.x *= sc; a0.y *= sc; a0.z *= sc; a0.w *= sc;
    a1.x *= sc; a1.y *= sc; a1.z *= sc; a1.w *= sc;
    float h0 = bf_hi(a0.x), h1 = bf_hi(a0.y), h2 = bf_hi(a0.z), h3 = bf_hi(a0.w);
    float h4 = bf_hi(a1.x), h5 = bf_hi(a1.y), h6 = bf_hi(a1.z), h7 = bf_hi(a1.w);
    uint2* mh = (uint2*)g_mhi + (size_t)warp * 64;
    uint2* ml = (uint2*)g_mlo + (size_t)warp * 64;
    mh[lane]      = make_uint2(pk(h0, h1), pk(h2, h3));
    mh[lane + 32] = make_uint2(pk(h4, h5), pk(h6, h7));
    ml[lane]      = make_uint2(pk(a0.x - h0, a0.y - h1), pk(a0.z - h2, a0.w - h3));
    ml[lane + 32] = make_uint2(pk(a1.x - h4, a1.y - h5), pk(a1.z - h6, a1.w - h7));
}
__global__ void convW_kernel(const float* __restrict__ W1l, const float* __restrict__ W1r,
                             const float* __restrict__ W2l, const float* __restrict__ W2r) {
    int t = blockIdx.x * blockDim.x + threadIdx.x;
    if (t >= 2 * 256 * 512) return;
    int layer = t >> 17;
    int rem = t & 131071;
    int n = rem >> 9;
    int k = rem & 511;
    const float* Wl = layer ? W2l : W1l;
    const float* Wr = layer ? W2r : W1r;
    float v = (k < 256) ? Wl[k * 256 + n] : Wr[(k - 256) * 256 + n];
    __nv_bfloat16 h = __float2bfloat16_rn(v);
    g_Bhi[t] = h;
    g_Blo[t] = __float2bfloat16_rn(v - __bfloat162float(h));
}

// ---------------- persistent pipelined mma.sync GEMM (R9-proven) ----------------
#define ROWB 80
#define STAGEB 40960
#define SM_GEMM (2 * STAGEB)

__global__ void __launch_bounds__(256, 2)
gemm_mma_kernel(const __nv_bfloat16* __restrict__ Amhi, const __nv_bfloat16* __restrict__ Amlo,
                const __nv_bfloat16* __restrict__ Axhi, const __nv_bfloat16* __restrict__ Axlo,
                const __nv_bfloat16* __restrict__ Bhi, const __nv_bfloat16* __restrict__ Blo,
                const float* __restrict__ bias, float* __restrict__ Cf,
                __nv_bfloat16* __restrict__ Chi, __nv_bfloat16* __restrict__ Clo,
                __half* __restrict__ Cf16, int M, int ntiles) {
    extern __shared__ char smem[];
    uint32_t sb = smem_u32(smem);
    int tid = threadIdx.x;
    int wid = tid >> 5, lane = tid & 31;
    int wm = wid >> 1, wn = wid & 1;
    int qr = lane >> 2, qc = (lane & 3) * 2;
    int lr = lane & 7, lg = lane >> 3;

    int stride = gridDim.x;
    int count = (ntiles - (int)blockIdx.x + stride - 1) / stride;
    if (count <= 0) return;
    int total_i = count * 16;

    float acc[2][8][4];
#pragma unroll
    for (int i = 0; i < 2; i++)
#pragma unroll
        for (int j = 0; j < 8; j++)
#pragma unroll
            for (int v = 0; v < 4; v++) acc[i][j][v] = 0.f;

    auto issue_i = [&](int gi, int stage) {
        int t = (int)blockIdx.x + (gi >> 4) * stride;
        int c = gi & 15;
        int bm = (t >> 1) * 128;
        int bn = (t & 1) * 128;
        const __nv_bfloat16* Ah = (c < 8) ? Amhi : Axhi;
        const __nv_bfloat16* Al = (c < 8) ? Amlo : Axlo;
        int kl = (c & 7) * 32;
        int k0 = c * 32;
        uint32_t sbase = sb + stage * STAGEB;
#pragma unroll
        for (int it = 0; it < 8; it++) {
            int item = it * 256 + tid;
            int arr = item >> 9, rem = item & 511, r = rem >> 2, kg = rem & 3;
            uint32_t dst = sbase + arr * 10240 + r * ROWB + kg * 16;
            const __nv_bfloat16* src;
            if (arr < 2) {
                int ar = bm + r; if (ar >= M) ar = M - 1;
                src = (arr == 0 ? Ah : Al) + (size_t)ar * 256 + kl + kg * 8;
            } else {
                src = (arr == 2 ? Bhi : Blo) + (size_t)(bn + r) * 512 + k0 + kg * 8;
            }
            CP_ASYNC16(dst, src);
        }
        CP_COMMIT();
    };

    issue_i(0, 0);
    for (int gi = 0; gi < total_i; gi++) {
        int st = gi & 1;
        if (gi + 1 < total_i) {
            issue_i(gi + 1, st ^ 1);
            asm volatile("cp.async.wait_group 1;" ::: "memory");
        } else {
            asm volatile("cp.async.wait_group 0;" ::: "memory");
        }
        __syncthreads();

        uint32_t Ahb = sb + st * STAGEB;
        uint32_t Alb = Ahb + 10240;
        uint32_t Bhb = Ahb + 20480;
        uint32_t Blb = Ahb + 30720;
        int arow0 = wm * 32 + lr + ((lg & 1) << 3);
        int brow0 = wn * 64 + lr + ((lg >> 1) << 3);
#pragma unroll
        for (int k16 = 0; k16 < 32; k16 += 16) {
            uint32_t akofs = (uint32_t)((k16 + ((lg >> 1) << 3)) * 2);
            uint32_t bkofs = (uint32_t)((k16 + ((lg & 1) << 3)) * 2);
            uint32_t ah[2][4], al[2][4];
            ldsm_x4(ah[0], Ahb + arow0 * ROWB + akofs);
            ldsm_x4(ah[1], Ahb + (arow0 + 16) * ROWB + akofs);
            ldsm_x4(al[0], Alb + arow0 * ROWB + akofs);
            ldsm_x4(al[1], Alb + (arow0 + 16) * ROWB + akofs);
#pragma unroll
            for (int p = 0; p < 4; p++) {
                uint32_t bh[4], bl[4];
                ldsm_x4(bh, Bhb + (brow0 + p * 16) * ROWB + bkofs);
                ldsm_x4(bl, Blb + (brow0 + p * 16) * ROWB + bkofs);
#pragma unroll
                for (int mt = 0; mt < 2; mt++)
#pragma unroll
                    for (int j = 0; j < 2; j++)
                        mma_bf16(acc[mt][p * 2 + j], ah[mt], &bh[2 * j]);
#pragma unroll
                for (int mt = 0; mt < 2; mt++)
#pragma unroll
                    for (int j = 0; j < 2; j++)
                        mma_bf16(acc[mt][p * 2 + j], ah[mt], &bl[2 * j]);
#pragma unroll
                for (int mt = 0; mt < 2; mt++)
#pragma unroll
                    for (int j = 0; j < 2; j++)
                        mma_bf16(acc[mt][p * 2 + j], al[mt], &bh[2 * j]);
            }
        }
        __syncthreads();

        if ((gi & 15) == 15) {
            int t = (int)blockIdx.x + (gi >> 4) * stride;
            int bm = (t >> 1) * 128;
            int bn = (t & 1) * 128;
#pragma unroll
            for (int mt = 0; mt < 2; mt++) {
                int r0 = bm + wm * 32 + mt * 16 + qr;
#pragma unroll
                for (int nt = 0; nt < 8; nt++) {
                    int col = bn + wn * 64 + nt * 8 + qc;
                    float2 bv = __ldg((const float2*)&bias[col]);
                    float v00 = acc[mt][nt][0] + bv.x, v01 = acc[mt][nt][1] + bv.y;
                    float v10 = acc[mt][nt][2] + bv.x, v11 = acc[mt][nt][3] + bv.y;
                    if (Cf) {
                        if (r0 < M)
                            *(float2*)&Cf[(size_t)r0 * 256 + col] = make_float2(v00, v01);
                        if (r0 + 8 < M)
                            *(float2*)&Cf[(size_t)(r0 + 8) * 256 + col] = make_float2(v10, v11);
                    }
                    if (Chi) {
                        if (r0 < M) {
                            float h0 = bf_hi(v00), h1 = bf_hi(v01);
                            size_t o = ((size_t)r0 * 256 + col) >> 1;
                            ((uint32_t*)Chi)[o] = pk(h0, h1);
                            ((uint32_t*)Clo)[o] = pk(v00 - h0, v01 - h1);
                            ((uint32_t*)Cf16)[o] = pkh(v00, v01);
                        }
                        if (r0 + 8 < M) {
                            float h0 = bf_hi(v10), h1 = bf_hi(v11);
                            size_t o = ((size_t)(r0 + 8) * 256 + col) >> 1;
                            ((uint32_t*)Chi)[o] = pk(h0, h1);
                            ((uint32_t*)Clo)[o] = pk(v10 - h0, v11 - h1);
                            ((uint32_t*)Cf16)[o] = pkh(v10, v11);
                        }
                    }
                }
            }
#pragma unroll
            for (int i = 0; i < 2; i++)
#pragma unroll
                for (int j = 0; j < 8; j++)
#pragma unroll
                    for (int v = 0; v < 4; v++) acc[i][j][v] = 0.f;
        }
    }
}

__global__ void gather_out_kernel(const float* __restrict__ xf,
                                  const int* __restrict__ idxA, int nA,
                                  const int* __restrict__ idxB,
                                  float* __restrict__ out) {
    int r = blockIdx.x;
    int srow = (r < nA) ? idxA[r] : idxB[r - nA];
    ((float4*)(out + (size_t)r * D256))[threadIdx.x] =
        ((const float4*)(xf + (size_t)srow * D256))[threadIdx.x];
}

extern "C" void kernel_launch(void* const* d_in, const int* in_sizes, int n_in,
                              void* d_out, int out_size) {
    const float* emb = (const float*)d_in[0];
    const float* W1l = (const float*)d_in[1];
    const float* b1l = (const float*)d_in[2];
    const float* W1r = (const float*)d_in[3];
    const float* W2l = (const float*)d_in[4];
    const float* b2l = (const float*)d_in[5];
    const float* W2r = (const float*)d_in[6];
    const int* x_idx = (const int*)d_in[7];
    const int* edge  = (const int*)d_in[8];
    const int* drug  = (const int*)d_in[9];
    const int* se    = (const int*)d_in[10];

    int N = in_sizes[7];
    int E = in_sizes[8] / 2;
    const int* src = edge;
    const int* dst = edge + E;
    int nd = in_sizes[9];
    int ns = in_sizes[10];

    float* out   = (float*)d_out;
    float* out_x = out + (size_t)(nd + ns) * D256;

    __nv_bfloat16 *pxhi, *pxlo, *phhi, *phlo, *pmhi, *pmlo, *pbh, *pbl;
    __half *pxf, *phf;
    cudaGetSymbolAddress((void**)&pxhi, g_xhi);
    cudaGetSymbolAddress((void**)&pxlo, g_xlo);
    cudaGetSymbolAddress((void**)&pxf,  g_xf16);
    cudaGetSymbolAddress((void**)&phhi, g_hhi);
    cudaGetSymbolAddress((void**)&phlo, g_hlo);
    cudaGetSymbolAddress((void**)&phf,  g_hf16);
    cudaGetSymbolAddress((void**)&pmhi, g_mhi);
    cudaGetSymbolAddress((void**)&pmlo, g_mlo);
    cudaGetSymbolAddress((void**)&pbh, g_Bhi);
    cudaGetSymbolAddress((void**)&pbl, g_Blo);

    static int nsm = 0;
    if (!nsm) {
        cudaDeviceGetAttribute(&nsm, cudaDevAttrMultiProcessorCount, 0);
        if (nsm <= 0) nsm = 148;
        cudaFuncSetAttribute(gemm_mma_kernel,
                             cudaFuncAttributeMaxDynamicSharedMemorySize, SM_GEMM);
    }

    int nb = (N + SCAN_BLK - 1) / SCAN_BLK;
    int ntiles = 2 * ((N + 127) / 128);
    int pgrid = 2 * nsm;
    if (pgrid > ntiles) pgrid = ntiles;

    // --- CSR build + input gather + weight conversion ---
    zero_cnt_kernel<<<(N + 255) / 256, 256>>>(N);
    gather_x_kernel<<<(N * 32 + 255) / 256, 256>>>(emb, x_idx, N);
    convW_kernel<<<(2 * 256 * 512 + 255) / 256, 256>>>(W1l, W1r, W2l, W2r);
    hist_kernel<<<(E + 255) / 256, 256>>>(dst, E);
    scan_local_kernel<<<nb, SCAN_BLK>>>(N);
    scan_part_kernel<<<1, 128>>>(nb);
    scan_final_kernel<<<nb, SCAN_BLK>>>(N);
    scatter_kernel<<<(E + 255) / 256, 256>>>(src, dst, E);

    // --- layer 1: agg(x fp16) -> mean hi/lo ; GEMM -> h hi/lo + fp16 ---
    aggregate_kernel<<<(N * 32 + 255) / 256, 256>>>(pxf, N);
    gemm_mma_kernel<<<pgrid, 256, SM_GEMM>>>(pmhi, pmlo, pxhi, pxlo, pbh, pbl,
                                             b1l, nullptr, phhi, phlo, phf, N, ntiles);

    // --- layer 2: agg(h fp16) -> mean hi/lo ; GEMM -> out_x fp32 ---
    aggregate_kernel<<<(N * 32 + 255) / 256, 256>>>(phf, N);
    gemm_mma_kernel<<<pgrid, 256, SM_GEMM>>>(pmhi, pmlo, phhi, phlo,
                                             pbh + 256 * 512, pbl + 256 * 512,
                                             b2l, out_x, nullptr, nullptr, nullptr,
                                             N, ntiles);

    // --- output gathers ---
    gather_out_kernel<<<nd + ns, 64>>>(out_x, drug, nd, se, out);
}

// round 15
// speedup vs baseline: 1.8377x; 1.3442x over previous
#include <cuda_runtime.h>
#include <cuda_bf16.h>
#include <cuda_fp16.h>
#include <cstdint>

#define D256 256
#define NMAX 100000
#define EMAX 1600000
#define SCAN_BLK 1024

// ---------------- scratch (device globals) ----------------
__device__ __half g_xf16[(size_t)NMAX * D256];   // x plane (GEMM A + aggregation)
__device__ __half g_hf16[(size_t)NMAX * D256];   // h plane
__device__ __half g_mf16[(size_t)NMAX * D256];   // mean plane
__device__ int   g_cnt[NMAX + 1];
__device__ int   g_incl[NMAX + 1];
__device__ int   g_rowptr[NMAX + 2];
__device__ int   g_wptr[NMAX + 1];
__device__ int   g_col[EMAX];
__device__ int   g_part[256];
__device__ int   g_poff[256];
// pre-converted weights: [layer][n (256)][k (512)] fp16 hi/lo
__device__ __half g_Whi[2 * 256 * 512];
__device__ __half g_Wlo[2 * 256 * 512];

// ---------------- helpers ----------------
__device__ __forceinline__ uint32_t pkh(float a, float b) {
    __half2 h = __floats2half2_rn(a, b);
    return *(uint32_t*)&h;
}
__device__ __forceinline__ uint32_t smem_u32(const void* p) {
    uint32_t a;
    asm("{ .reg .u64 t; cvta.to.shared.u64 t, %1; cvt.u32.u64 %0, t; }"
        : "=r"(a) : "l"(p));
    return a;
}
__device__ __forceinline__ void mma_f16(float* c, const uint32_t* a, const uint32_t* b) {
    asm volatile(
        "mma.sync.aligned.m16n8k16.row.col.f32.f16.f16.f32 "
        "{%0,%1,%2,%3}, {%4,%5,%6,%7}, {%8,%9}, {%0,%1,%2,%3};"
        : "+f"(c[0]), "+f"(c[1]), "+f"(c[2]), "+f"(c[3])
        : "r"(a[0]), "r"(a[1]), "r"(a[2]), "r"(a[3]), "r"(b[0]), "r"(b[1]));
}
__device__ __forceinline__ void ldsm_x4(uint32_t* r, uint32_t addr) {
    asm volatile("ldmatrix.sync.aligned.m8n8.x4.shared.b16 {%0,%1,%2,%3}, [%4];"
                 : "=r"(r[0]), "=r"(r[1]), "=r"(r[2]), "=r"(r[3]) : "r"(addr));
}
#define CP_ASYNC16(dst, src) asm volatile( \
    "cp.async.cg.shared.global [%0], [%1], 16;" :: "r"(dst), "l"(src) : "memory")
#define CP_COMMIT() asm volatile("cp.async.commit_group;" ::: "memory")

// accumulate a packed half2 word into two fp32 accs
__device__ __forceinline__ void acc_h2(float& e, float& o, uint32_t w) {
    float2 f = __half22float2(*(const __half2*)&w);
    e += f.x; o += f.y;
}

// ---------------- small utility kernels ----------------
__global__ void zero_cnt_kernel(int n) {
    int i = blockIdx.x * blockDim.x + threadIdx.x;
    if (i < n) g_cnt[i] = 0;
}
// x = emb[x_idx]; writes single fp16 plane
__global__ void gather_x_kernel(const float* __restrict__ emb,
                                const int* __restrict__ idx, int N) {
    int t = blockIdx.x * blockDim.x + threadIdx.x;
    if (t >= N * 32) return;
    int r = t >> 5, c = t & 31;
    const float4* p = (const float4*)emb + (size_t)idx[r] * 64 + c * 2;
    float4 v0 = p[0], v1 = p[1];
    ((uint4*)g_xf16)[(size_t)r * 32 + c] =
        make_uint4(pkh(v0.x, v0.y), pkh(v0.z, v0.w), pkh(v1.x, v1.y), pkh(v1.z, v1.w));
}
__global__ void hist_kernel(const int* __restrict__ dst, int E) {
    int i = blockIdx.x * blockDim.x + threadIdx.x;
    if (i < E) atomicAdd(&g_cnt[dst[i]], 1);
}
__global__ void scan_local_kernel(int N) {
    __shared__ int s[SCAN_BLK];
    int i = blockIdx.x * SCAN_BLK + threadIdx.x;
    int v = (i < N) ? g_cnt[i] : 0;
    s[threadIdx.x] = v;
    __syncthreads();
    for (int off = 1; off < SCAN_BLK; off <<= 1) {
        int t = (threadIdx.x >= off) ? s[threadIdx.x - off] : 0;
        __syncthreads();
        s[threadIdx.x] += t;
        __syncthreads();
    }
    if (i < N) g_incl[i] = s[threadIdx.x];
    if (threadIdx.x == SCAN_BLK - 1) g_part[blockIdx.x] = s[SCAN_BLK - 1];
}
__global__ void scan_part_kernel(int nb) {
    __shared__ int s[128];
    int t = threadIdx.x;
    int v = (t < nb) ? g_part[t] : 0;
    s[t] = v;
    __syncthreads();
    for (int off = 1; off < 128; off <<= 1) {
        int u = (t >= off) ? s[t - off] : 0;
        __syncthreads();
        s[t] += u;
        __syncthreads();
    }
    if (t < nb) g_poff[t] = s[t] - v;   // exclusive
}
__global__ void scan_final_kernel(int N) {
    int i = blockIdx.x * SCAN_BLK + threadIdx.x;
    if (i < N) {
        int v = g_incl[i] + g_poff[blockIdx.x];
        g_rowptr[i + 1] = v;
        g_wptr[i] = v - g_cnt[i];
    }
    if (i == 0) g_rowptr[0] = 0;
}
__global__ void scatter_kernel(const int* __restrict__ src,
                               const int* __restrict__ dst, int E) {
    int i = blockIdx.x * blockDim.x + threadIdx.x;
    if (i < E) {
        int pos = atomicAdd(&g_wptr[dst[i]], 1);
        g_col[pos] = src[i];
    }
}
// mean aggregation: gathers fp16 plane, fp32 accumulate, writes fp16 mean plane
__global__ void aggregate_kernel(const __half* __restrict__ xf, int N) {
    int warp = (blockIdx.x * blockDim.x + threadIdx.x) >> 5;
    int lane = threadIdx.x & 31;
    if (warp >= N) return;
    int beg = g_rowptr[warp], end = g_rowptr[warp + 1];
    float4 a0 = make_float4(0.f, 0.f, 0.f, 0.f);
    float4 a1 = make_float4(0.f, 0.f, 0.f, 0.f);
    int j = beg;
    for (; j + 1 < end; j += 2) {
        const uint2* r0 = (const uint2*)(xf + (size_t)g_col[j] * D256);
        const uint2* r1 = (const uint2*)(xf + (size_t)g_col[j + 1] * D256);
        uint2 va0 = r0[lane], vb0 = r0[lane + 32];
        uint2 va1 = r1[lane], vb1 = r1[lane + 32];
        acc_h2(a0.x, a0.y, va0.x); acc_h2(a0.z, a0.w, va0.y);
        acc_h2(a1.x, a1.y, vb0.x); acc_h2(a1.z, a1.w, vb0.y);
        acc_h2(a0.x, a0.y, va1.x); acc_h2(a0.z, a0.w, va1.y);
        acc_h2(a1.x, a1.y, vb1.x); acc_h2(a1.z, a1.w, vb1.y);
    }
    if (j < end) {
        const uint2* r0 = (const uint2*)(xf + (size_t)g_col[j] * D256);
        uint2 va = r0[lane], vb = r0[lane + 32];
        acc_h2(a0.x, a0.y, va.x); acc_h2(a0.z, a0.w, va.y);
        acc_h2(a1.x, a1.y, vb.x); acc_h2(a1.z, a1.w, vb.y);
    }
    int deg = end - beg;
    float sc = 1.0f / (float)(deg > 1 ? deg : 1);
    uint2* mf = (uint2*)g_mf16 + (size_t)warp * 64;
    mf[lane]      = make_uint2(pkh(a0.x * sc, a0.y * sc), pkh(a0.z * sc, a0.w * sc));
    mf[lane + 32] = make_uint2(pkh(a1.x * sc, a1.y * sc), pkh(a1.z * sc, a1.w * sc));
}
// convert W (fp32, [k][n]) -> g_W (fp16 hi/lo, [layer][n][k]) once
__global__ void convW_kernel(const float* __restrict__ W1l, const float* __restrict__ W1r,
                             const float* __restrict__ W2l, const float* __restrict__ W2r) {
    int t = blockIdx.x * blockDim.x + threadIdx.x;
    if (t >= 2 * 256 * 512) return;
    int layer = t >> 17;
    int rem = t & 131071;
    int n = rem >> 9;
    int k = rem & 511;
    const float* Wl = layer ? W2l : W1l;
    const float* Wr = layer ? W2r : W1r;
    float v = (k < 256) ? Wl[k * 256 + n] : Wr[(k - 256) * 256 + n];
    __half h = __float2half_rn(v);
    g_Whi[t] = h;
    g_Wlo[t] = __float2half_rn(v - __half2float(h));
}

// ---------------- persistent pipelined fp16 mma GEMM ----------------
// C[M,256] = Am@Wl + Ax@Wr + bias; A single fp16, W fp16 hi/lo 2-term.
// CTA 256 thr, tile 128x128; warp tile 32x64. K: 16 chunks of 32 (8 Am, 8 Ax).
// Persistent grid, 2-stage cp.async pipeline across tile boundaries.
#define ROWB 80
#define STAGEB 30720
#define SM_GEMM (2 * STAGEB)

__global__ void __launch_bounds__(256, 2)
gemm_mma_kernel(const __half* __restrict__ Am, const __half* __restrict__ Ax,
                const __half* __restrict__ Whi, const __half* __restrict__ Wlo,
                const float* __restrict__ bias, float* __restrict__ Cf,
                __half* __restrict__ Ch, int M, int ntiles) {
    extern __shared__ char smem[];
    uint32_t sb = smem_u32(smem);
    int tid = threadIdx.x;
    int wid = tid >> 5, lane = tid & 31;
    int wm = wid >> 1, wn = wid & 1;
    int qr = lane >> 2, qc = (lane & 3) * 2;
    int lr = lane & 7, lg = lane >> 3;

    int stride = gridDim.x;
    int count = (ntiles - (int)blockIdx.x + stride - 1) / stride;
    if (count <= 0) return;
    int total_i = count * 16;

    float acc[2][8][4];
#pragma unroll
    for (int i = 0; i < 2; i++)
#pragma unroll
        for (int j = 0; j < 8; j++)
#pragma unroll
            for (int v = 0; v < 4; v++) acc[i][j][v] = 0.f;

    // chunk: A 128x32 fp16 (512 x16B) + Whi/Wlo 128x32 (512+512 x16B) = 1536, 6/thread
    auto issue_i = [&](int gi, int stage) {
        int t = (int)blockIdx.x + (gi >> 4) * stride;
        int c = gi & 15;
        int bm = (t >> 1) * 128;
        int bn = (t & 1) * 128;
        const __half* A = (c < 8) ? Am : Ax;
        int kl = (c & 7) * 32;
        int k0 = c * 32;
        uint32_t sbase = sb + stage * STAGEB;
#pragma unroll
        for (int it = 0; it < 6; it++) {
            int item = it * 256 + tid;          // 0..1535
            uint32_t dst;
            const __half* src;
            if (item < 512) {                   // A
                int r = item >> 2, kg = item & 3;
                int ar = bm + r; if (ar >= M) ar = M - 1;
                dst = sbase + r * ROWB + kg * 16;
                src = A + (size_t)ar * 256 + kl + kg * 8;
            } else {                            // W hi (512..1023), W lo (1024..1535)
                int itb = item - 512;
                int arr = itb >> 9, rem = itb & 511, n = rem >> 2, kg = rem & 3;
                dst = sbase + 10240 + arr * 10240 + n * ROWB + kg * 16;
                src = (arr == 0 ? Whi : Wlo) + (size_t)(bn + n) * 512 + k0 + kg * 8;
            }
            CP_ASYNC16(dst, src);
        }
        CP_COMMIT();
    };

    issue_i(0, 0);
    for (int gi = 0; gi < total_i; gi++) {
        int st = gi & 1;
        if (gi + 1 < total_i) {
            issue_i(gi + 1, st ^ 1);
            asm volatile("cp.async.wait_group 1;" ::: "memory");
        } else {
            asm volatile("cp.async.wait_group 0;" ::: "memory");
        }
        __syncthreads();

        uint32_t Ab  = sb + st * STAGEB;
        uint32_t Bhb = Ab + 10240;
        uint32_t Blb = Ab + 20480;
        int arow0 = wm * 32 + lr + ((lg & 1) << 3);
        int brow0 = wn * 64 + lr + ((lg >> 1) << 3);
#pragma unroll
        for (int k16 = 0; k16 < 32; k16 += 16) {
            uint32_t akofs = (uint32_t)((k16 + ((lg >> 1) << 3)) * 2);
            uint32_t bkofs = (uint32_t)((k16 + ((lg & 1) << 3)) * 2);
            uint32_t ah[2][4];
            ldsm_x4(ah[0], Ab + arow0 * ROWB + akofs);
            ldsm_x4(ah[1], Ab + (arow0 + 16) * ROWB + akofs);
#pragma unroll
            for (int p = 0; p < 4; p++) {
                uint32_t bh[4], bl[4];
                ldsm_x4(bh, Bhb + (brow0 + p * 16) * ROWB + bkofs);
                ldsm_x4(bl, Blb + (brow0 + p * 16) * ROWB + bkofs);
#pragma unroll
                for (int mt = 0; mt < 2; mt++)
#pragma unroll
                    for (int j = 0; j < 2; j++)
                        mma_f16(acc[mt][p * 2 + j], ah[mt], &bh[2 * j]);
#pragma unroll
                for (int mt = 0; mt < 2; mt++)
#pragma unroll
                    for (int j = 0; j < 2; j++)
                        mma_f16(acc[mt][p * 2 + j], ah[mt], &bl[2 * j]);
            }
        }
        __syncthreads();

        if ((gi & 15) == 15) {
            int t = (int)blockIdx.x + (gi >> 4) * stride;
            int bm = (t >> 1) * 128;
            int bn = (t & 1) * 128;
#pragma unroll
            for (int mt = 0; mt < 2; mt++) {
                int r0 = bm + wm * 32 + mt * 16 + qr;
#pragma unroll
                for (int nt = 0; nt < 8; nt++) {
                    int col = bn + wn * 64 + nt * 8 + qc;
                    float2 bv = __ldg((const float2*)&bias[col]);
                    float v00 = acc[mt][nt][0] + bv.x, v01 = acc[mt][nt][1] + bv.y;
                    float v10 = acc[mt][nt][2] + bv.x, v11 = acc[mt][nt][3] + bv.y;
                    if (Cf) {
                        if (r0 < M)
                            *(float2*)&Cf[(size_t)r0 * 256 + col] = make_float2(v00, v01);
                        if (r0 + 8 < M)
                            *(float2*)&Cf[(size_t)(r0 + 8) * 256 + col] = make_float2(v10, v11);
                    }
                    if (Ch) {
                        if (r0 < M)
                            ((uint32_t*)Ch)[((size_t)r0 * 256 + col) >> 1] = pkh(v00, v01);
                        if (r0 + 8 < M)
                            ((uint32_t*)Ch)[((size_t)(r0 + 8) * 256 + col) >> 1] = pkh(v10, v11);
                    }
                }
            }
#pragma unroll
            for (int i = 0; i < 2; i++)
#pragma unroll
                for (int j = 0; j < 8; j++)
#pragma unroll
                    for (int v = 0; v < 4; v++) acc[i][j][v] = 0.f;
        }
    }
}

__global__ void gather_out_kernel(const float* __restrict__ xf,
                                  const int* __restrict__ idxA, int nA,
                                  const int* __restrict__ idxB,
                                  float* __restrict__ out) {
    int r = blockIdx.x;
    int srow = (r < nA) ? idxA[r] : idxB[r - nA];
    ((float4*)(out + (size_t)r * D256))[threadIdx.x] =
        ((const float4*)(xf + (size_t)srow * D256))[threadIdx.x];
}

extern "C" void kernel_launch(void* const* d_in, const int* in_sizes, int n_in,
                              void* d_out, int out_size) {
    const float* emb = (const float*)d_in[0];
    const float* W1l = (const float*)d_in[1];
    const float* b1l = (const float*)d_in[2];
    const float* W1r = (const float*)d_in[3];
    const float* W2l = (const float*)d_in[4];
    const float* b2l = (const float*)d_in[5];
    const float* W2r = (const float*)d_in[6];
    const int* x_idx = (const int*)d_in[7];
    const int* edge  = (const int*)d_in[8];
    const int* drug  = (const int*)d_in[9];
    const int* se    = (const int*)d_in[10];

    int N = in_sizes[7];
    int E = in_sizes[8] / 2;
    const int* src = edge;
    const int* dst = edge + E;
    int nd = in_sizes[9];
    int ns = in_sizes[10];

    float* out   = (float*)d_out;
    float* out_x = out + (size_t)(nd + ns) * D256;

    __half *pxf, *phf, *pmf, *pwh, *pwl;
    cudaGetSymbolAddress((void**)&pxf, g_xf16);
    cudaGetSymbolAddress((void**)&phf, g_hf16);
    cudaGetSymbolAddress((void**)&pmf, g_mf16);
    cudaGetSymbolAddress((void**)&pwh, g_Whi);
    cudaGetSymbolAddress((void**)&pwl, g_Wlo);

    static int nsm = 0;
    if (!nsm) {
        cudaDeviceGetAttribute(&nsm, cudaDevAttrMultiProcessorCount, 0);
        if (nsm <= 0) nsm = 148;
        cudaFuncSetAttribute(gemm_mma_kernel,
                             cudaFuncAttributeMaxDynamicSharedMemorySize, SM_GEMM);
    }

    int nb = (N + SCAN_BLK - 1) / SCAN_BLK;
    int ntiles = 2 * ((N + 127) / 128);
    int pgrid = 2 * nsm;
    if (pgrid > ntiles) pgrid = ntiles;

    // --- CSR build + input gather + weight conversion ---
    zero_cnt_kernel<<<(N + 255) / 256, 256>>>(N);
    gather_x_kernel<<<(N * 32 + 255) / 256, 256>>>(emb, x_idx, N);
    convW_kernel<<<(2 * 256 * 512 + 255) / 256, 256>>>(W1l, W1r, W2l, W2r);
    hist_kernel<<<(E + 255) / 256, 256>>>(dst, E);
    scan_local_kernel<<<nb, SCAN_BLK>>>(N);
    scan_part_kernel<<<1, 128>>>(nb);
    scan_final_kernel<<<nb, SCAN_BLK>>>(N);
    scatter_kernel<<<(E + 255) / 256, 256>>>(src, dst, E);

    // --- layer 1: agg(x fp16) -> mean fp16 ; GEMM -> h fp16 ---
    aggregate_kernel<<<(N * 32 + 255) / 256, 256>>>(pxf, N);
    gemm_mma_kernel<<<pgrid, 256, SM_GEMM>>>(pmf, pxf, pwh, pwl,
                                             b1l, nullptr, phf, N, ntiles);

    // --- layer 2: agg(h fp16) -> mean fp16 ; GEMM -> out_x fp32 ---
    aggregate_kernel<<<(N * 32 + 255) / 256, 256>>>(phf, N);
    gemm_mma_kernel<<<pgrid, 256, SM_GEMM>>>(pmf, phf, pwh + 256 * 512, pwl + 256 * 512,
                                             b2l, out_x, nullptr, N, ntiles);

    // --- output gathers ---
    gather_out_kernel<<<nd + ns, 64>>>(out_x, drug, nd, se, out);
}

// round 16
// speedup vs baseline: 2.5007x; 1.3607x over previous
#include <cuda_runtime.h>
#include <cuda_bf16.h>
#include <cuda_fp16.h>
#include <cstdint>

#define D256 256
#define NMAX 100000
#define EMAX 1600000
#define SCAN_BLK 1024

// ---------------- scratch (device globals) ----------------
__device__ __half g_xf16[(size_t)NMAX * D256];   // x plane (GEMM A + aggregation)
__device__ __half g_hf16[(size_t)NMAX * D256];   // h plane
__device__ __half g_mf16[(size_t)NMAX * D256];   // mean plane
__device__ int   g_cnt[NMAX + 1];
__device__ int   g_incl[NMAX + 1];
__device__ int   g_rowptr[NMAX + 2];
__device__ int   g_wptr[NMAX + 1];
__device__ int   g_col[EMAX];
__device__ int   g_part[256];
__device__ int   g_poff[256];
// pre-converted weights: [layer][n (256)][k (512)] fp16
__device__ __half g_Whi[2 * 256 * 512];

// ---------------- helpers ----------------
__device__ __forceinline__ uint32_t pkh(float a, float b) {
    __half2 h = __floats2half2_rn(a, b);
    return *(uint32_t*)&h;
}
__device__ __forceinline__ uint32_t smem_u32(const void* p) {
    uint32_t a;
    asm("{ .reg .u64 t; cvta.to.shared.u64 t, %1; cvt.u32.u64 %0, t; }"
        : "=r"(a) : "l"(p));
    return a;
}
__device__ __forceinline__ void mma_f16(float* c, const uint32_t* a, const uint32_t* b) {
    asm volatile(
        "mma.sync.aligned.m16n8k16.row.col.f32.f16.f16.f32 "
        "{%0,%1,%2,%3}, {%4,%5,%6,%7}, {%8,%9}, {%0,%1,%2,%3};"
        : "+f"(c[0]), "+f"(c[1]), "+f"(c[2]), "+f"(c[3])
        : "r"(a[0]), "r"(a[1]), "r"(a[2]), "r"(a[3]), "r"(b[0]), "r"(b[1]));
}
__device__ __forceinline__ void ldsm_x4(uint32_t* r, uint32_t addr) {
    asm volatile("ldmatrix.sync.aligned.m8n8.x4.shared.b16 {%0,%1,%2,%3}, [%4];"
                 : "=r"(r[0]), "=r"(r[1]), "=r"(r[2]), "=r"(r[3]) : "r"(addr));
}
#define CP_ASYNC16(dst, src) asm volatile( \
    "cp.async.cg.shared.global [%0], [%1], 16;" :: "r"(dst), "l"(src) : "memory")
#define CP_COMMIT() asm volatile("cp.async.commit_group;" ::: "memory")

// accumulate a packed half2 word into two fp32 accs
__device__ __forceinline__ void acc_h2(float& e, float& o, uint32_t w) {
    float2 f = __half22float2(*(const __half2*)&w);
    e += f.x; o += f.y;
}

// ---------------- small utility kernels ----------------
__global__ void zero_cnt_kernel(int n) {
    int i = blockIdx.x * blockDim.x + threadIdx.x;
    if (i < n) g_cnt[i] = 0;
}
// x = emb[x_idx]; writes single fp16 plane
__global__ void gather_x_kernel(const float* __restrict__ emb,
                                const int* __restrict__ idx, int N) {
    int t = blockIdx.x * blockDim.x + threadIdx.x;
    if (t >= N * 32) return;
    int r = t >> 5, c = t & 31;
    const float4* p = (const float4*)emb + (size_t)idx[r] * 64 + c * 2;
    float4 v0 = p[0], v1 = p[1];
    ((uint4*)g_xf16)[(size_t)r * 32 + c] =
        make_uint4(pkh(v0.x, v0.y), pkh(v0.z, v0.w), pkh(v1.x, v1.y), pkh(v1.z, v1.w));
}
__global__ void hist_kernel(const int* __restrict__ dst, int E) {
    int i = blockIdx.x * blockDim.x + threadIdx.x;
    if (i < E) atomicAdd(&g_cnt[dst[i]], 1);
}
__global__ void scan_local_kernel(int N) {
    __shared__ int s[SCAN_BLK];
    int i = blockIdx.x * SCAN_BLK + threadIdx.x;
    int v = (i < N) ? g_cnt[i] : 0;
    s[threadIdx.x] = v;
    __syncthreads();
    for (int off = 1; off < SCAN_BLK; off <<= 1) {
        int t = (threadIdx.x >= off) ? s[threadIdx.x - off] : 0;
        __syncthreads();
        s[threadIdx.x] += t;
        __syncthreads();
    }
    if (i < N) g_incl[i] = s[threadIdx.x];
    if (threadIdx.x == SCAN_BLK - 1) g_part[blockIdx.x] = s[SCAN_BLK - 1];
}
__global__ void scan_part_kernel(int nb) {
    __shared__ int s[128];
    int t = threadIdx.x;
    int v = (t < nb) ? g_part[t] : 0;
    s[t] = v;
    __syncthreads();
    for (int off = 1; off < 128; off <<= 1) {
        int u = (t >= off) ? s[t - off] : 0;
        __syncthreads();
        s[t] += u;
        __syncthreads();
    }
    if (t < nb) g_poff[t] = s[t] - v;   // exclusive
}
__global__ void scan_final_kernel(int N) {
    int i = blockIdx.x * SCAN_BLK + threadIdx.x;
    if (i < N) {
        int v = g_incl[i] + g_poff[blockIdx.x];
        g_rowptr[i + 1] = v;
        g_wptr[i] = v - g_cnt[i];
    }
    if (i == 0) g_rowptr[0] = 0;
}
__global__ void scatter_kernel(const int* __restrict__ src,
                               const int* __restrict__ dst, int E) {
    int i = blockIdx.x * blockDim.x + threadIdx.x;
    if (i < E) {
        int pos = atomicAdd(&g_wptr[dst[i]], 1);
        g_col[pos] = src[i];
    }
}
// mean aggregation: gathers fp16 plane, fp32 accumulate, writes fp16 mean plane
__global__ void aggregate_kernel(const __half* __restrict__ xf, int N) {
    int warp = (blockIdx.x * blockDim.x + threadIdx.x) >> 5;
    int lane = threadIdx.x & 31;
    if (warp >= N) return;
    int beg = g_rowptr[warp], end = g_rowptr[warp + 1];
    float4 a0 = make_float4(0.f, 0.f, 0.f, 0.f);
    float4 a1 = make_float4(0.f, 0.f, 0.f, 0.f);
    int j = beg;
    for (; j + 1 < end; j += 2) {
        const uint2* r0 = (const uint2*)(xf + (size_t)g_col[j] * D256);
        const uint2* r1 = (const uint2*)(xf + (size_t)g_col[j + 1] * D256);
        uint2 va0 = r0[lane], vb0 = r0[lane + 32];
        uint2 va1 = r1[lane], vb1 = r1[lane + 32];
        acc_h2(a0.x, a0.y, va0.x); acc_h2(a0.z, a0.w, va0.y);
        acc_h2(a1.x, a1.y, vb0.x); acc_h2(a1.z, a1.w, vb0.y);
        acc_h2(a0.x, a0.y, va1.x); acc_h2(a0.z, a0.w, va1.y);
        acc_h2(a1.x, a1.y, vb1.x); acc_h2(a1.z, a1.w, vb1.y);
    }
    if (j < end) {
        const uint2* r0 = (const uint2*)(xf + (size_t)g_col[j] * D256);
        uint2 va = r0[lane], vb = r0[lane + 32];
        acc_h2(a0.x, a0.y, va.x); acc_h2(a0.z, a0.w, va.y);
        acc_h2(a1.x, a1.y, vb.x); acc_h2(a1.z, a1.w, vb.y);
    }
    int deg = end - beg;
    float sc = 1.0f / (float)(deg > 1 ? deg : 1);
    uint2* mf = (uint2*)g_mf16 + (size_t)warp * 64;
    mf[lane]      = make_uint2(pkh(a0.x * sc, a0.y * sc), pkh(a0.z * sc, a0.w * sc));
    mf[lane + 32] = make_uint2(pkh(a1.x * sc, a1.y * sc), pkh(a1.z * sc, a1.w * sc));
}
// convert W (fp32, [k][n]) -> g_Whi (fp16, [layer][n][k]) once
__global__ void convW_kernel(const float* __restrict__ W1l, const float* __restrict__ W1r,
                             const float* __restrict__ W2l, const float* __restrict__ W2r) {
    int t = blockIdx.x * blockDim.x + threadIdx.x;
    if (t >= 2 * 256 * 512) return;
    int layer = t >> 17;
    int rem = t & 131071;
    int n = rem >> 9;
    int k = rem & 511;
    const float* Wl = layer ? W2l : W1l;
    const float* Wr = layer ? W2r : W1r;
    float v = (k < 256) ? Wl[k * 256 + n] : Wr[(k - 256) * 256 + n];
    g_Whi[t] = __float2half_rn(v);
}

// ---------------- persistent pipelined fp16 mma GEMM ----------------
// C[M,256] = Am@Wl + Ax@Wr + bias; A fp16, W fp16 (single term).
// CTA 256 thr, tile 128x128; warp tile 32x64. K: 16 chunks of 32 (8 Am, 8 Ax).
// Persistent grid, 2-stage cp.async pipeline across tile boundaries.
#define ROWB 80
#define STAGEB 20480
#define SM_GEMM (2 * STAGEB)

__global__ void __launch_bounds__(256, 2)
gemm_mma_kernel(const __half* __restrict__ Am, const __half* __restrict__ Ax,
                const __half* __restrict__ Whi,
                const float* __restrict__ bias, float* __restrict__ Cf,
                __half* __restrict__ Ch, int M, int ntiles) {
    extern __shared__ char smem[];
    uint32_t sb = smem_u32(smem);
    int tid = threadIdx.x;
    int wid = tid >> 5, lane = tid & 31;
    int wm = wid >> 1, wn = wid & 1;
    int qr = lane >> 2, qc = (lane & 3) * 2;
    int lr = lane & 7, lg = lane >> 3;

    int stride = gridDim.x;
    int count = (ntiles - (int)blockIdx.x + stride - 1) / stride;
    if (count <= 0) return;
    int total_i = count * 16;

    float acc[2][8][4];
#pragma unroll
    for (int i = 0; i < 2; i++)
#pragma unroll
        for (int j = 0; j < 8; j++)
#pragma unroll
            for (int v = 0; v < 4; v++) acc[i][j][v] = 0.f;

    // chunk: A 128x32 fp16 (512 x16B) + W 128x32 (512 x16B) = 1024, 4/thread
    auto issue_i = [&](int gi, int stage) {
        int t = (int)blockIdx.x + (gi >> 4) * stride;
        int c = gi & 15;
        int bm = (t >> 1) * 128;
        int bn = (t & 1) * 128;
        const __half* A = (c < 8) ? Am : Ax;
        int kl = (c & 7) * 32;
        int k0 = c * 32;
        uint32_t sbase = sb + stage * STAGEB;
#pragma unroll
        for (int it = 0; it < 4; it++) {
            int item = it * 256 + tid;          // 0..1023
            uint32_t dst;
            const __half* src;
            if (item < 512) {                   // A
                int r = item >> 2, kg = item & 3;
                int ar = bm + r; if (ar >= M) ar = M - 1;
                dst = sbase + r * ROWB + kg * 16;
                src = A + (size_t)ar * 256 + kl + kg * 8;
            } else {                            // W
                int itb = item - 512;
                int n = itb >> 2, kg = itb & 3;
                dst = sbase + 10240 + n * ROWB + kg * 16;
                src = Whi + (size_t)(bn + n) * 512 + k0 + kg * 8;
            }
            CP_ASYNC16(dst, src);
        }
        CP_COMMIT();
    };

    issue_i(0, 0);
    for (int gi = 0; gi < total_i; gi++) {
        int st = gi & 1;
        if (gi + 1 < total_i) {
            issue_i(gi + 1, st ^ 1);
            asm volatile("cp.async.wait_group 1;" ::: "memory");
        } else {
            asm volatile("cp.async.wait_group 0;" ::: "memory");
        }
        __syncthreads();

        uint32_t Ab  = sb + st * STAGEB;
        uint32_t Bhb = Ab + 10240;
        int arow0 = wm * 32 + lr + ((lg & 1) << 3);
        int brow0 = wn * 64 + lr + ((lg >> 1) << 3);
#pragma unroll
        for (int k16 = 0; k16 < 32; k16 += 16) {
            uint32_t akofs = (uint32_t)((k16 + ((lg >> 1) << 3)) * 2);
            uint32_t bkofs = (uint32_t)((k16 + ((lg & 1) << 3)) * 2);
            uint32_t ah[2][4];
            ldsm_x4(ah[0], Ab + arow0 * ROWB + akofs);
            ldsm_x4(ah[1], Ab + (arow0 + 16) * ROWB + akofs);
#pragma unroll
            for (int p = 0; p < 4; p++) {
                uint32_t bh[4];
                ldsm_x4(bh, Bhb + (brow0 + p * 16) * ROWB + bkofs);
#pragma unroll
                for (int mt = 0; mt < 2; mt++)
#pragma unroll
                    for (int j = 0; j < 2; j++)
                        mma_f16(acc[mt][p * 2 + j], ah[mt], &bh[2 * j]);
            }
        }
        __syncthreads();

        if ((gi & 15) == 15) {
            int t = (int)blockIdx.x + (gi >> 4) * stride;
            int bm = (t >> 1) * 128;
            int bn = (t & 1) * 128;
#pragma unroll
            for (int mt = 0; mt < 2; mt++) {
                int r0 = bm + wm * 32 + mt * 16 + qr;
#pragma unroll
                for (int nt = 0; nt < 8; nt++) {
                    int col = bn + wn * 64 + nt * 8 + qc;
                    float2 bv = __ldg((const float2*)&bias[col]);
                    float v00 = acc[mt][nt][0] + bv.x, v01 = acc[mt][nt][1] + bv.y;
                    float v10 = acc[mt][nt][2] + bv.x, v11 = acc[mt][nt][3] + bv.y;
                    if (Cf) {
                        if (r0 < M)
                            *(float2*)&Cf[(size_t)r0 * 256 + col] = make_float2(v00, v01);
                        if (r0 + 8 < M)
                            *(float2*)&Cf[(size_t)(r0 + 8) * 256 + col] = make_float2(v10, v11);
                    }
                    if (Ch) {
                        if (r0 < M)
                            ((uint32_t*)Ch)[((size_t)r0 * 256 + col) >> 1] = pkh(v00, v01);
                        if (r0 + 8 < M)
                            ((uint32_t*)Ch)[((size_t)(r0 + 8) * 256 + col) >> 1] = pkh(v10, v11);
                    }
                }
            }
#pragma unroll
            for (int i = 0; i < 2; i++)
#pragma unroll
                for (int j = 0; j < 8; j++)
#pragma unroll
                    for (int v = 0; v < 4; v++) acc[i][j][v] = 0.f;
        }
    }
}

__global__ void gather_out_kernel(const float* __restrict__ xf,
                                  const int* __restrict__ idxA, int nA,
                                  const int* __restrict__ idxB,
                                  float* __restrict__ out) {
    int r = blockIdx.x;
    int srow = (r < nA) ? idxA[r] : idxB[r - nA];
    ((float4*)(out + (size_t)r * D256))[threadIdx.x] =
        ((const float4*)(xf + (size_t)srow * D256))[threadIdx.x];
}

extern "C" void kernel_launch(void* const* d_in, const int* in_sizes, int n_in,
                              void* d_out, int out_size) {
    const float* emb = (const float*)d_in[0];
    const float* W1l = (const float*)d_in[1];
    const float* b1l = (const float*)d_in[2];
    const float* W1r = (const float*)d_in[3];
    const float* W2l = (const float*)d_in[4];
    const float* b2l = (const float*)d_in[5];
    const float* W2r = (const float*)d_in[6];
    const int* x_idx = (const int*)d_in[7];
    const int* edge  = (const int*)d_in[8];
    const int* drug  = (const int*)d_in[9];
    const int* se    = (const int*)d_in[10];

    int N = in_sizes[7];
    int E = in_sizes[8] / 2;
    const int* src = edge;
    const int* dst = edge + E;
    int nd = in_sizes[9];
    int ns = in_sizes[10];

    float* out   = (float*)d_out;
    float* out_x = out + (size_t)(nd + ns) * D256;

    __half *pxf, *phf, *pmf, *pwh;
    cudaGetSymbolAddress((void**)&pxf, g_xf16);
    cudaGetSymbolAddress((void**)&phf, g_hf16);
    cudaGetSymbolAddress((void**)&pmf, g_mf16);
    cudaGetSymbolAddress((void**)&pwh, g_Whi);

    static int nsm = 0;
    if (!nsm) {
        cudaDeviceGetAttribute(&nsm, cudaDevAttrMultiProcessorCount, 0);
        if (nsm <= 0) nsm = 148;
        cudaFuncSetAttribute(gemm_mma_kernel,
                             cudaFuncAttributeMaxDynamicSharedMemorySize, SM_GEMM);
    }

    int nb = (N + SCAN_BLK - 1) / SCAN_BLK;
    int ntiles = 2 * ((N + 127) / 128);
    int pgrid = 2 * nsm;
    if (pgrid > ntiles) pgrid = ntiles;

    // --- CSR build + input gather + weight conversion ---
    zero_cnt_kernel<<<(N + 255) / 256, 256>>>(N);
    gather_x_kernel<<<(N * 32 + 255) / 256, 256>>>(emb, x_idx, N);
    convW_kernel<<<(2 * 256 * 512 + 255) / 256, 256>>>(W1l, W1r, W2l, W2r);
    hist_kernel<<<(E + 255) / 256, 256>>>(dst, E);
    scan_local_kernel<<<nb, SCAN_BLK>>>(N);
    scan_part_kernel<<<1, 128>>>(nb);
    scan_final_kernel<<<nb, SCAN_BLK>>>(N);
    scatter_kernel<<<(E + 255) / 256, 256>>>(src, dst, E);

    // --- layer 1: agg(x fp16) -> mean fp16 ; GEMM -> h fp16 ---
    aggregate_kernel<<<(N * 32 + 255) / 256, 256>>>(pxf, N);
    gemm_mma_kernel<<<pgrid, 256, SM_GEMM>>>(pmf, pxf, pwh,
                                             b1l, nullptr, phf, N, ntiles);

    // --- layer 2: agg(h fp16) -> mean fp16 ; GEMM -> out_x fp32 ---
    aggregate_kernel<<<(N * 32 + 255) / 256, 256>>>(phf, N);
    gemm_mma_kernel<<<pgrid, 256, SM_GEMM>>>(pmf, phf, pwh + 256 * 512,
                                             b2l, out_x, nullptr, N, ntiles);

    // --- output gathers ---
    gather_out_kernel<<<nd + ns, 64>>>(out_x, drug, nd, se, out);
}